// round 1
// baseline (speedup 1.0000x reference)
#include <cuda_runtime.h>
#include <cuda_bf16.h>
#include <math.h>
#include <stdint.h>

// ---------------- problem constants ----------------
#define BATCH 128
#define CH    3
#define HIM   224
#define PGRID 14          // P
#define NP    196         // P*P patches
#define PATCH 16
#define IN_D  768         // C*PATCH*PATCH
#define DMODEL 256
#define NHEAD 8
#define DH    32
#define NLAYER 4
#define SEQ   197         // NP + 1
#define OUTC  1000
#define LNEPS 1e-5f

// ---------------- scratch (device globals; no allocations allowed) ----------
__device__ float g_patches[BATCH * NP * IN_D];           // 77 MB
__device__ float g_X [BATCH * SEQ * DMODEL];             // 25.8 MB
__device__ float g_x1[BATCH * SEQ * DMODEL];
__device__ float g_q [BATCH * SEQ * DMODEL];             // layout [n,h,s,e]
__device__ float g_k [BATCH * SEQ * DMODEL];
__device__ float g_v [BATCH * SEQ * DMODEL];
__device__ float g_o [BATCH * SEQ * DMODEL];             // layout [n,s,d]
__device__ float g_h1[BATCH * SEQ * 4 * DMODEL];         // 103 MB (also tokens tmp)
__device__ float g_pe[SEQ * DMODEL];

// ---------------- patch extraction ----------------
__global__ void patch_kernel(const float* __restrict__ img, float* __restrict__ out)
{
    int idx = blockIdx.x * 256 + threadIdx.x;
    if (idx >= BATCH * NP * IN_D) return;
    int i = idx % IN_D;
    int p = (idx / IN_D) % NP;
    int n = idx / (IN_D * NP);
    int c   = i >> 8;          // /256
    int r   = (i >> 4) & 15;
    int col = i & 15;
    int py = p / PGRID, px = p % PGRID;
    out[idx] = img[(((size_t)n * CH + c) * HIM + py * PATCH + r) * HIM + px * PATCH + col];
}

// ---------------- positional encoding table (fp64 for accuracy) ------------
__global__ void pe_kernel(float* __restrict__ pe)
{
    int i = blockIdx.x * 256 + threadIdx.x;
    if (i >= SEQ * DMODEL) return;
    int s = i / DMODEL, d = i % DMODEL;
    double expo = (double)(2 * (d / 2)) / (double)DMODEL;
    double ang  = (double)s / pow(10000.0, expo);
    pe[i] = (float)((d & 1) ? cos(ang) : sin(ang));
}

// ---------------- assemble X = concat(cls, tokens) + pe --------------------
__global__ void assemble_kernel(const float* __restrict__ tok,
                                const float* __restrict__ cls,
                                const float* __restrict__ pe,
                                float* __restrict__ X)
{
    int i = blockIdx.x * 256 + threadIdx.x;
    if (i >= BATCH * SEQ * DMODEL) return;
    int d = i % DMODEL;
    int s = (i / DMODEL) % SEQ;
    int n = i / (SEQ * DMODEL);
    float v = (s == 0) ? cls[d]
                       : tok[((size_t)n * NP + (s - 1)) * DMODEL + d];
    X[i] = v + pe[s * DMODEL + d];
}

// ---------------- generic tiled GEMM:  C = act(A @ W^T + bias) (+res) ------
// A: [M,K] row-major, W: [N,K] row-major. Requires M%64==0, N%64==0, K%16==0.
template<int ACT, bool HASRES>
__global__ void gemm_kernel(const float* __restrict__ A,
                            const float* __restrict__ W,
                            const float* __restrict__ bias,
                            const float* __restrict__ res,
                            float* __restrict__ C,
                            int M, int N, int K)
{
    __shared__ __align__(16) float As[16][64];
    __shared__ __align__(16) float Ws[16][64];
    const int t  = threadIdx.x;           // 256 threads
    const int tx = t & 15, ty = t >> 4;
    const int row0 = blockIdx.y * 64, col0 = blockIdx.x * 64;
    const int lr = t >> 2;                 // 0..63
    const int lc = (t & 3) << 2;           // 0,4,8,12
    const float* Ap = A + (size_t)(row0 + lr) * K + lc;
    const float* Wp = W + (size_t)(col0 + lr) * K + lc;

    float acc[4][4];
#pragma unroll
    for (int i = 0; i < 4; i++)
#pragma unroll
        for (int j = 0; j < 4; j++) acc[i][j] = 0.f;

    for (int k0 = 0; k0 < K; k0 += 16) {
        float4 av = *(const float4*)(Ap + k0);
        float4 wv = *(const float4*)(Wp + k0);
        As[lc + 0][lr] = av.x; As[lc + 1][lr] = av.y;
        As[lc + 2][lr] = av.z; As[lc + 3][lr] = av.w;
        Ws[lc + 0][lr] = wv.x; Ws[lc + 1][lr] = wv.y;
        Ws[lc + 2][lr] = wv.z; Ws[lc + 3][lr] = wv.w;
        __syncthreads();
#pragma unroll
        for (int kk = 0; kk < 16; kk++) {
            float4 a = *(const float4*)&As[kk][ty << 2];
            float4 b = *(const float4*)&Ws[kk][tx << 2];
            float ar[4] = {a.x, a.y, a.z, a.w};
            float br[4] = {b.x, b.y, b.z, b.w};
#pragma unroll
            for (int i = 0; i < 4; i++)
#pragma unroll
                for (int j = 0; j < 4; j++) acc[i][j] += ar[i] * br[j];
        }
        __syncthreads();
    }

    const int n0 = col0 + (tx << 2);
    float4 bv4 = *(const float4*)(bias + n0);
    float bb[4] = {bv4.x, bv4.y, bv4.z, bv4.w};
#pragma unroll
    for (int i = 0; i < 4; i++) {
        int m = row0 + (ty << 2) + i;
        float v[4];
#pragma unroll
        for (int j = 0; j < 4; j++) {
            float x = acc[i][j] + bb[j];
            if (ACT == 1) x = 0.5f * x * (1.0f + erff(x * 0.70710678118654752f));
            v[j] = x;
        }
        if (HASRES) {
            float4 r4 = *(const float4*)(res + (size_t)m * N + n0);
            v[0] += r4.x; v[1] += r4.y; v[2] += r4.z; v[3] += r4.w;
        }
        float4 o4 = make_float4(v[0], v[1], v[2], v[3]);
        *(float4*)(C + (size_t)m * N + n0) = o4;
    }
}

// ---------------- LayerNorm (one block of 256 per row, D=256) --------------
__global__ void layernorm_kernel(const float* __restrict__ x,
                                 const float* __restrict__ g,
                                 const float* __restrict__ b,
                                 float* __restrict__ y)
{
    __shared__ float red[8];
    const int row = blockIdx.x;
    const int t = threadIdx.x, wid = t >> 5, lane = t & 31;
    float v = x[(size_t)row * DMODEL + t];

    float s = v;
#pragma unroll
    for (int off = 16; off; off >>= 1) s += __shfl_xor_sync(0xffffffffu, s, off);
    if (lane == 0) red[wid] = s;
    __syncthreads();
    float mu = 0.f;
#pragma unroll
    for (int i = 0; i < 8; i++) mu += red[i];
    mu *= (1.f / DMODEL);
    __syncthreads();

    float dv = v - mu;
    float s2 = dv * dv;
#pragma unroll
    for (int off = 16; off; off >>= 1) s2 += __shfl_xor_sync(0xffffffffu, s2, off);
    if (lane == 0) red[wid] = s2;
    __syncthreads();
    float var = 0.f;
#pragma unroll
    for (int i = 0; i < 8; i++) var += red[i];
    var *= (1.f / DMODEL);

    y[(size_t)row * DMODEL + t] = dv * rsqrtf(var + LNEPS) * g[t] + b[t];
}

// ---------------- fused per-head QKV projection -----------------------------
// grid: (B*H, ceil(S/8)), block 256. q/k/v out layout [n,h,s,e].
__global__ void qkv_kernel(const float* __restrict__ x1,
                           const float* __restrict__ wq, const float* __restrict__ bq,
                           const float* __restrict__ wk, const float* __restrict__ bk,
                           const float* __restrict__ wv, const float* __restrict__ bv,
                           float* __restrict__ q, float* __restrict__ k, float* __restrict__ v)
{
    __shared__ float wqs[32 * 33], wks[32 * 33], wvs[32 * 33];
    __shared__ float bqs[32], bks[32], bvs[32];
    __shared__ float xr[8][32];
    const int nh = blockIdx.x;
    const int n = nh / NHEAD, h = nh % NHEAD;
    const int t = threadIdx.x;
    const float* wqg = wq + (size_t)h * DH * DH;
    const float* wkg = wk + (size_t)h * DH * DH;
    const float* wvg = wv + (size_t)h * DH * DH;

    for (int i = t; i < DH * DH; i += 256) {
        int e = i >> 5, d = i & 31;
        wqs[e * 33 + d] = wqg[i];
        wks[e * 33 + d] = wkg[i];
        wvs[e * 33 + d] = wvg[i];
    }
    if (t < 32) { bqs[t] = bq[h * DH + t]; bks[t] = bk[h * DH + t]; bvs[t] = bv[h * DH + t]; }

    const int sl = t >> 5, lane = t & 31;
    const int s = blockIdx.y * 8 + sl;
    if (s < SEQ) xr[sl][lane] = x1[((size_t)n * SEQ + s) * DMODEL + h * DH + lane];
    __syncthreads();
    if (s >= SEQ) return;

    float aq = bqs[lane], ak = bks[lane], av = bvs[lane];
#pragma unroll
    for (int d = 0; d < 32; d++) {
        float xv = xr[sl][d];
        aq += xv * wqs[lane * 33 + d];
        ak += xv * wks[lane * 33 + d];
        av += xv * wvs[lane * 33 + d];
    }
    size_t oidx = ((size_t)nh * SEQ + s) * DH + lane;
    q[oidx] = aq; k[oidx] = ak; v[oidx] = av;
}

// ---------------- fused attention per (n,h): QK^T -> softmax -> PV ----------
// grid: B*H blocks, 256 threads, dynamic smem. o out layout [n,s,d].
__global__ void attn_kernel(const float* __restrict__ q, const float* __restrict__ k,
                            const float* __restrict__ v, float* __restrict__ o)
{
    extern __shared__ float sm[];
    float* Ks    = sm;                         // SEQ*33 (padded)
    float* Vs    = Ks + SEQ * 33;              // SEQ*32
    float* probs = Vs + SEQ * 32;              // 8*SEQ
    float* qs    = probs + 8 * SEQ;            // 8*32

    const int nh = blockIdx.x;
    const int n = nh / NHEAD, h = nh % NHEAD;
    const int t = threadIdx.x, wid = t >> 5, lane = t & 31;
    const size_t base = (size_t)nh * SEQ * DH;

    for (int i = t; i < SEQ * DH; i += 256) {
        int tt = i >> 5, e = i & 31;
        Ks[tt * 33 + e] = k[base + i];
        Vs[i]           = v[base + i];
    }
    __syncthreads();

    const float scale = 0.17677669529663689f;  // 1/sqrt(32)

    for (int s = wid; s < SEQ; s += 8) {
        float qv = q[base + (size_t)s * DH + lane];
        qs[wid * 32 + lane] = qv;
        __syncwarp();

        float sc[7];
        float mx = -1e30f;
        int cnt = 0;
        for (int t0 = lane; t0 < SEQ; t0 += 32) {
            float acc = 0.f;
#pragma unroll
            for (int e = 0; e < 32; e++) acc += qs[wid * 32 + e] * Ks[t0 * 33 + e];
            acc *= scale;
            sc[cnt++] = acc;
            mx = fmaxf(mx, acc);
        }
#pragma unroll
        for (int off = 16; off; off >>= 1) mx = fmaxf(mx, __shfl_xor_sync(0xffffffffu, mx, off));

        float sum = 0.f;
        cnt = 0;
        for (int t0 = lane; t0 < SEQ; t0 += 32) {
            float p = __expf(sc[cnt++] - mx);
            probs[wid * SEQ + t0] = p;
            sum += p;
        }
#pragma unroll
        for (int off = 16; off; off >>= 1) sum += __shfl_xor_sync(0xffffffffu, sum, off);
        __syncwarp();

        float inv = 1.f / sum;
        float oe = 0.f;
        for (int t0 = 0; t0 < SEQ; t0++) oe += probs[wid * SEQ + t0] * Vs[t0 * 32 + lane];
        o[((size_t)n * SEQ + s) * DMODEL + h * DH + lane] = oe * inv;
        __syncwarp();   // before qs/probs reuse next iteration
    }
}

// ---------------- classification head: logits + softmax --------------------
__global__ void head_kernel(const float* __restrict__ X, const float* __restrict__ w_out,
                            const float* __restrict__ b_out, float* __restrict__ out)
{
    __shared__ float cls_s[DMODEL];
    __shared__ float logits[OUTC];
    __shared__ float red[8];
    const int n = blockIdx.x;
    const int t = threadIdx.x, wid = t >> 5, lane = t & 31;

    cls_s[t] = X[(size_t)n * SEQ * DMODEL + t];
    __syncthreads();

    for (int j = wid; j < OUTC; j += 8) {
        float acc = 0.f;
#pragma unroll
        for (int k = lane; k < DMODEL; k += 32) acc += cls_s[k] * w_out[(size_t)j * DMODEL + k];
#pragma unroll
        for (int off = 16; off; off >>= 1) acc += __shfl_xor_sync(0xffffffffu, acc, off);
        if (lane == 0) logits[j] = acc + b_out[j];
    }
    __syncthreads();

    float mx = -1e30f;
    for (int j = t; j < OUTC; j += 256) mx = fmaxf(mx, logits[j]);
#pragma unroll
    for (int off = 16; off; off >>= 1) mx = fmaxf(mx, __shfl_xor_sync(0xffffffffu, mx, off));
    if (lane == 0) red[wid] = mx;
    __syncthreads();
    float bm = -1e30f;
#pragma unroll
    for (int i = 0; i < 8; i++) bm = fmaxf(bm, red[i]);
    __syncthreads();

    float sum = 0.f;
    for (int j = t; j < OUTC; j += 256) {
        float e = __expf(logits[j] - bm);
        logits[j] = e;
        sum += e;
    }
#pragma unroll
    for (int off = 16; off; off >>= 1) sum += __shfl_xor_sync(0xffffffffu, sum, off);
    if (lane == 0) red[wid] = sum;
    __syncthreads();
    float bs = 0.f;
#pragma unroll
    for (int i = 0; i < 8; i++) bs += red[i];
    float inv = 1.f / bs;
    __syncthreads();
    for (int j = t; j < OUTC; j += 256) out[(size_t)n * OUTC + j] = logits[j] * inv;
}

// ---------------- launcher ----------------
extern "C" void kernel_launch(void* const* d_in, const int* in_sizes, int n_in,
                              void* d_out, int out_size)
{
    const float* images  = (const float*)d_in[0];
    const float* w_map   = (const float*)d_in[1];
    const float* b_map   = (const float*)d_in[2];
    const float* cls_tok = (const float*)d_in[3];
    const float* norm1_g = (const float*)d_in[4];
    const float* norm1_b = (const float*)d_in[5];
    const float* wq      = (const float*)d_in[6];
    const float* bq      = (const float*)d_in[7];
    const float* wk      = (const float*)d_in[8];
    const float* bk      = (const float*)d_in[9];
    const float* wv      = (const float*)d_in[10];
    const float* bv      = (const float*)d_in[11];
    const float* w_last  = (const float*)d_in[12];
    const float* b_last  = (const float*)d_in[13];
    const float* norm2_g = (const float*)d_in[14];
    const float* norm2_b = (const float*)d_in[15];
    const float* w_mlp1  = (const float*)d_in[16];
    const float* b_mlp1  = (const float*)d_in[17];
    const float* w_mlp2  = (const float*)d_in[18];
    const float* b_mlp2  = (const float*)d_in[19];
    const float* w_out   = (const float*)d_in[20];
    const float* b_out   = (const float*)d_in[21];
    float* out = (float*)d_out;

    float *patches, *X, *x1, *qb, *kb, *vb, *ob, *h1, *pe;
    cudaGetSymbolAddress((void**)&patches, g_patches);
    cudaGetSymbolAddress((void**)&X,  g_X);
    cudaGetSymbolAddress((void**)&x1, g_x1);
    cudaGetSymbolAddress((void**)&qb, g_q);
    cudaGetSymbolAddress((void**)&kb, g_k);
    cudaGetSymbolAddress((void**)&vb, g_v);
    cudaGetSymbolAddress((void**)&ob, g_o);
    cudaGetSymbolAddress((void**)&h1, g_h1);
    cudaGetSymbolAddress((void**)&pe, g_pe);

    const int attn_smem = (SEQ * 33 + SEQ * 32 + 8 * SEQ + 8 * 32) * (int)sizeof(float);
    cudaFuncSetAttribute(attn_kernel, cudaFuncAttributeMaxDynamicSharedMemorySize, attn_smem);

    // 1) patches + PE table
    {
        int tot = BATCH * NP * IN_D;
        patch_kernel<<<(tot + 255) / 256, 256>>>(images, patches);
        int pt = SEQ * DMODEL;
        pe_kernel<<<(pt + 255) / 256, 256>>>(pe);
    }

    // 2) patch-embed GEMM: tokens(tmp in h1) = patches @ w_map^T + b_map
    //    M = 25088 (=64*392), N = 256, K = 768
    gemm_kernel<0, false><<<dim3(DMODEL / 64, (BATCH * NP) / 64), 256>>>(
        patches, w_map, b_map, nullptr, h1, BATCH * NP, DMODEL, IN_D);

    // 3) X = concat(cls, tokens) + pe
    {
        int tot = BATCH * SEQ * DMODEL;
        assemble_kernel<<<(tot + 255) / 256, 256>>>(h1, cls_tok, pe, X);
    }

    const int MROWS = BATCH * SEQ;   // 25216 = 64*394

    for (int l = 0; l < NLAYER; l++) {
        // LN1
        layernorm_kernel<<<MROWS, 256>>>(X, norm1_g + l * DMODEL, norm1_b + l * DMODEL, x1);

        // QKV
        qkv_kernel<<<dim3(BATCH * NHEAD, (SEQ + 7) / 8), 256>>>(
            x1,
            wq + (size_t)l * NHEAD * DH * DH, bq + (size_t)l * NHEAD * DH,
            wk + (size_t)l * NHEAD * DH * DH, bk + (size_t)l * NHEAD * DH,
            wv + (size_t)l * NHEAD * DH * DH, bv + (size_t)l * NHEAD * DH,
            qb, kb, vb);

        // attention
        attn_kernel<<<BATCH * NHEAD, 256, attn_smem>>>(qb, kb, vb, ob);

        // o-proj + residual: X = X + o @ w_last^T + b_last   (M,N,K = 25216,256,256)
        gemm_kernel<0, true><<<dim3(DMODEL / 64, MROWS / 64), 256>>>(
            ob, w_last + (size_t)l * DMODEL * DMODEL, b_last + l * DMODEL, X, X,
            MROWS, DMODEL, DMODEL);

        // LN2 -> x1 (reused as x2)
        layernorm_kernel<<<MROWS, 256>>>(X, norm2_g + l * DMODEL, norm2_b + l * DMODEL, x1);

        // MLP1 + GELU: h1 = gelu(x2 @ w_mlp1^T + b1)   (25216,1024,256)
        gemm_kernel<1, false><<<dim3((4 * DMODEL) / 64, MROWS / 64), 256>>>(
            x1, w_mlp1 + (size_t)l * 4 * DMODEL * DMODEL, b_mlp1 + l * 4 * DMODEL,
            nullptr, h1, MROWS, 4 * DMODEL, DMODEL);

        // MLP2 + residual: X = X + h1 @ w_mlp2^T + b2   (25216,256,1024)
        gemm_kernel<0, true><<<dim3(DMODEL / 64, MROWS / 64), 256>>>(
            h1, w_mlp2 + (size_t)l * 4 * DMODEL * DMODEL, b_mlp2 + l * DMODEL, X, X,
            MROWS, DMODEL, 4 * DMODEL);
    }

    // head: logits on cls token + softmax
    head_kernel<<<BATCH, 256>>>(X, w_out, b_out, out);
}

// round 2
// speedup vs baseline: 1.5563x; 1.5563x over previous
#include <cuda_runtime.h>
#include <cuda_bf16.h>
#include <math.h>
#include <stdint.h>

// ---------------- problem constants ----------------
#define BATCH 128
#define CH    3
#define HIM   224
#define PGRID 14          // P
#define NP    196         // P*P patches
#define PATCH 16
#define IN_D  768         // C*PATCH*PATCH
#define DMODEL 256
#define NHEAD 8
#define DH    32
#define NLAYER 4
#define SEQ   197         // NP + 1
#define OUTC  1000
#define LNEPS 1e-5f

// ---------------- scratch (device globals; no allocations allowed) ----------
__device__ float g_patches[BATCH * NP * IN_D];           // 77 MB
__device__ float g_X [BATCH * SEQ * DMODEL];             // 25.8 MB
__device__ float g_x1[BATCH * SEQ * DMODEL];
__device__ float g_q [BATCH * SEQ * DMODEL];             // layout [n,h,s,e]
__device__ float g_k [BATCH * SEQ * DMODEL];
__device__ float g_v [BATCH * SEQ * DMODEL];
__device__ float g_o [BATCH * SEQ * DMODEL];             // layout [n,s,d]
__device__ float g_h1[BATCH * SEQ * 4 * DMODEL];         // 103 MB (also tokens tmp)
__device__ float g_pe[SEQ * DMODEL];

// ---------------- patch extraction ----------------
__global__ void patch_kernel(const float* __restrict__ img, float* __restrict__ out)
{
    int idx = blockIdx.x * 256 + threadIdx.x;
    if (idx >= BATCH * NP * IN_D) return;
    int i = idx % IN_D;
    int p = (idx / IN_D) % NP;
    int n = idx / (IN_D * NP);
    int c   = i >> 8;
    int r   = (i >> 4) & 15;
    int col = i & 15;
    int py = p / PGRID, px = p % PGRID;
    out[idx] = img[(((size_t)n * CH + c) * HIM + py * PATCH + r) * HIM + px * PATCH + col];
}

// ---------------- positional encoding table (fp64 for accuracy) ------------
__global__ void pe_kernel(float* __restrict__ pe)
{
    int i = blockIdx.x * 256 + threadIdx.x;
    if (i >= SEQ * DMODEL) return;
    int s = i / DMODEL, d = i % DMODEL;
    double expo = (double)(2 * (d / 2)) / (double)DMODEL;
    double ang  = (double)s / pow(10000.0, expo);
    pe[i] = (float)((d & 1) ? cos(ang) : sin(ang));
}

// ---------------- assemble X = concat(cls, tokens) + pe --------------------
__global__ void assemble_kernel(const float* __restrict__ tok,
                                const float* __restrict__ cls,
                                const float* __restrict__ pe,
                                float* __restrict__ X)
{
    int i = blockIdx.x * 256 + threadIdx.x;
    if (i >= BATCH * SEQ * DMODEL) return;
    int d = i % DMODEL;
    int s = (i / DMODEL) % SEQ;
    int n = i / (SEQ * DMODEL);
    float v = (s == 0) ? cls[d]
                       : tok[((size_t)n * NP + (s - 1)) * DMODEL + d];
    X[i] = v + pe[s * DMODEL + d];
}

// ---------------- tf32 tensor-core GEMM -------------------------------------
// C = act(A @ W^T + bias) (+res). A:[M,K] row-major, W:[N,K] row-major.
// Block tile 128(M) x 64(N), K-tile 32, 8 warps, double-buffered SMEM.
// Requires M%128==0, N%64==0, K%32==0.
__device__ __forceinline__ uint32_t f2tf32(float x)
{
    uint32_t r;
    asm("cvt.rna.tf32.f32 %0, %1;" : "=r"(r) : "f"(x));
    return r;
}

__device__ __forceinline__ void mma_tf32(float* c, const uint32_t* a, const uint32_t* b)
{
    asm volatile(
        "mma.sync.aligned.m16n8k8.row.col.f32.tf32.tf32.f32 "
        "{%0,%1,%2,%3}, {%4,%5,%6,%7}, {%8,%9}, {%0,%1,%2,%3};"
        : "+f"(c[0]), "+f"(c[1]), "+f"(c[2]), "+f"(c[3])
        : "r"(a[0]), "r"(a[1]), "r"(a[2]), "r"(a[3]), "r"(b[0]), "r"(b[1]));
}

#define A_BUF (128 * 36)
#define B_BUF (64 * 36)
#define GEMM_SMEM ((2 * A_BUF + 2 * B_BUF) * 4)

template<int ACT, bool HASRES>
__global__ void __launch_bounds__(256) gemm_tc(const float* __restrict__ A,
                                               const float* __restrict__ W,
                                               const float* __restrict__ bias,
                                               const float* __restrict__ res,
                                               float* __restrict__ C,
                                               int M, int N, int K)
{
    extern __shared__ uint32_t sm_[];
    uint32_t* Asb[2] = { sm_,            sm_ + A_BUF };
    uint32_t* Bsb[2] = { sm_ + 2 * A_BUF, sm_ + 2 * A_BUF + B_BUF };

    const int t    = threadIdx.x;
    const int warp = t >> 5, lane = t & 31;
    const int g    = lane >> 2, q4 = lane & 3;
    const int warp_m = (warp >> 1) * 32;
    const int warp_n = (warp & 1) * 32;
    const int row0 = blockIdx.y * 128, col0 = blockIdx.x * 64;

    float acc[2][4][4];
#pragma unroll
    for (int mi = 0; mi < 2; mi++)
#pragma unroll
        for (int ni = 0; ni < 4; ni++)
#pragma unroll
            for (int e = 0; e < 4; e++) acc[mi][ni][e] = 0.f;

    // staging index precompute: A tile 128x32 (1024 float4), B tile 64x32 (512 float4)
    int a_r[4], a_c[4];
#pragma unroll
    for (int i = 0; i < 4; i++) { int f = t + i * 256; a_r[i] = f >> 3; a_c[i] = (f & 7) << 2; }
    int b_r[2], b_c[2];
#pragma unroll
    for (int i = 0; i < 2; i++) { int f = t + i * 256; b_r[i] = f >> 3; b_c[i] = (f & 7) << 2; }

    float4 ar[4], br[2];

    auto loadG = [&](int k0) {
#pragma unroll
        for (int i = 0; i < 4; i++)
            ar[i] = *(const float4*)(A + (size_t)(row0 + a_r[i]) * K + k0 + a_c[i]);
#pragma unroll
        for (int i = 0; i < 2; i++)
            br[i] = *(const float4*)(W + (size_t)(col0 + b_r[i]) * K + k0 + b_c[i]);
    };
    auto storeS = [&](int buf) {
#pragma unroll
        for (int i = 0; i < 4; i++) {
            uint32_t* d = Asb[buf] + a_r[i] * 36 + a_c[i];
            d[0] = f2tf32(ar[i].x); d[1] = f2tf32(ar[i].y);
            d[2] = f2tf32(ar[i].z); d[3] = f2tf32(ar[i].w);
        }
#pragma unroll
        for (int i = 0; i < 2; i++) {
            uint32_t* d = Bsb[buf] + b_r[i] * 36 + b_c[i];
            d[0] = f2tf32(br[i].x); d[1] = f2tf32(br[i].y);
            d[2] = f2tf32(br[i].z); d[3] = f2tf32(br[i].w);
        }
    };

    const int KT = K >> 5;
    loadG(0);
    storeS(0);
    __syncthreads();

    for (int kt = 0; kt < KT; kt++) {
        const int cur = kt & 1;
        if (kt + 1 < KT) loadG((kt + 1) << 5);

        const uint32_t* Ab = Asb[cur];
        const uint32_t* Bb = Bsb[cur];
#pragma unroll
        for (int ks = 0; ks < 4; ks++) {
            const int k = ks << 3;
            uint32_t af[2][4];
#pragma unroll
            for (int mi = 0; mi < 2; mi++) {
                int r = warp_m + mi * 16 + g;
                af[mi][0] = Ab[r * 36 + k + q4];
                af[mi][1] = Ab[(r + 8) * 36 + k + q4];
                af[mi][2] = Ab[r * 36 + k + q4 + 4];
                af[mi][3] = Ab[(r + 8) * 36 + k + q4 + 4];
            }
            uint32_t bf[4][2];
#pragma unroll
            for (int ni = 0; ni < 4; ni++) {
                int n = warp_n + ni * 8 + g;
                bf[ni][0] = Bb[n * 36 + k + q4];
                bf[ni][1] = Bb[n * 36 + k + q4 + 4];
            }
#pragma unroll
            for (int mi = 0; mi < 2; mi++)
#pragma unroll
                for (int ni = 0; ni < 4; ni++)
                    mma_tf32(acc[mi][ni], af[mi], bf[ni]);
        }

        if (kt + 1 < KT) storeS(1 - cur);
        __syncthreads();
    }

    // epilogue: bias (+gelu) (+residual), fp32
#pragma unroll
    for (int mi = 0; mi < 2; mi++) {
        int ra = row0 + warp_m + mi * 16 + g;
        int rb = ra + 8;
#pragma unroll
        for (int ni = 0; ni < 4; ni++) {
            int col = col0 + warp_n + ni * 8 + q4 * 2;
            float b0 = bias[col], b1 = bias[col + 1];
            float v00 = acc[mi][ni][0] + b0, v01 = acc[mi][ni][1] + b1;
            float v10 = acc[mi][ni][2] + b0, v11 = acc[mi][ni][3] + b1;
            if (ACT == 1) {
                v00 = 0.5f * v00 * (1.0f + erff(v00 * 0.70710678118654752f));
                v01 = 0.5f * v01 * (1.0f + erff(v01 * 0.70710678118654752f));
                v10 = 0.5f * v10 * (1.0f + erff(v10 * 0.70710678118654752f));
                v11 = 0.5f * v11 * (1.0f + erff(v11 * 0.70710678118654752f));
            }
            if (HASRES) {
                float2 r0 = *(const float2*)(res + (size_t)ra * N + col);
                float2 r1 = *(const float2*)(res + (size_t)rb * N + col);
                v00 += r0.x; v01 += r0.y; v10 += r1.x; v11 += r1.y;
            }
            *(float2*)(C + (size_t)ra * N + col) = make_float2(v00, v01);
            *(float2*)(C + (size_t)rb * N + col) = make_float2(v10, v11);
        }
    }
}

// ---------------- LayerNorm (one block of 256 per row, D=256) --------------
__global__ void layernorm_kernel(const float* __restrict__ x,
                                 const float* __restrict__ g,
                                 const float* __restrict__ b,
                                 float* __restrict__ y)
{
    __shared__ float red[8];
    const int row = blockIdx.x;
    const int t = threadIdx.x, wid = t >> 5, lane = t & 31;
    float v = x[(size_t)row * DMODEL + t];

    float s = v;
#pragma unroll
    for (int off = 16; off; off >>= 1) s += __shfl_xor_sync(0xffffffffu, s, off);
    if (lane == 0) red[wid] = s;
    __syncthreads();
    float mu = 0.f;
#pragma unroll
    for (int i = 0; i < 8; i++) mu += red[i];
    mu *= (1.f / DMODEL);
    __syncthreads();

    float dv = v - mu;
    float s2 = dv * dv;
#pragma unroll
    for (int off = 16; off; off >>= 1) s2 += __shfl_xor_sync(0xffffffffu, s2, off);
    if (lane == 0) red[wid] = s2;
    __syncthreads();
    float var = 0.f;
#pragma unroll
    for (int i = 0; i < 8; i++) var += red[i];
    var *= (1.f / DMODEL);

    y[(size_t)row * DMODEL + t] = dv * rsqrtf(var + LNEPS) * g[t] + b[t];
}

// ---------------- fused per-head QKV projection -----------------------------
__global__ void qkv_kernel(const float* __restrict__ x1,
                           const float* __restrict__ wq, const float* __restrict__ bq,
                           const float* __restrict__ wk, const float* __restrict__ bk,
                           const float* __restrict__ wv, const float* __restrict__ bv,
                           float* __restrict__ q, float* __restrict__ k, float* __restrict__ v)
{
    __shared__ float wqs[32 * 33], wks[32 * 33], wvs[32 * 33];
    __shared__ float bqs[32], bks[32], bvs[32];
    __shared__ float xr[8][32];
    const int nh = blockIdx.x;
    const int n = nh / NHEAD, h = nh % NHEAD;
    const int t = threadIdx.x;
    const float* wqg = wq + (size_t)h * DH * DH;
    const float* wkg = wk + (size_t)h * DH * DH;
    const float* wvg = wv + (size_t)h * DH * DH;

    for (int i = t; i < DH * DH; i += 256) {
        int e = i >> 5, d = i & 31;
        wqs[e * 33 + d] = wqg[i];
        wks[e * 33 + d] = wkg[i];
        wvs[e * 33 + d] = wvg[i];
    }
    if (t < 32) { bqs[t] = bq[h * DH + t]; bks[t] = bk[h * DH + t]; bvs[t] = bv[h * DH + t]; }

    const int sl = t >> 5, lane = t & 31;
    const int s = blockIdx.y * 8 + sl;
    if (s < SEQ) xr[sl][lane] = x1[((size_t)n * SEQ + s) * DMODEL + h * DH + lane];
    __syncthreads();
    if (s >= SEQ) return;

    float aq = bqs[lane], ak = bks[lane], av = bvs[lane];
#pragma unroll
    for (int d = 0; d < 32; d++) {
        float xv = xr[sl][d];
        aq += xv * wqs[lane * 33 + d];
        ak += xv * wks[lane * 33 + d];
        av += xv * wvs[lane * 33 + d];
    }
    size_t oidx = ((size_t)nh * SEQ + s) * DH + lane;
    q[oidx] = aq; k[oidx] = ak; v[oidx] = av;
}

// ---------------- fused attention per (n,h) ---------------------------------
__global__ void attn_kernel(const float* __restrict__ q, const float* __restrict__ k,
                            const float* __restrict__ v, float* __restrict__ o)
{
    extern __shared__ float sm[];
    float* Ks    = sm;
    float* Vs    = Ks + SEQ * 33;
    float* probs = Vs + SEQ * 32;
    float* qs    = probs + 8 * SEQ;

    const int nh = blockIdx.x;
    const int n = nh / NHEAD, h = nh % NHEAD;
    const int t = threadIdx.x, wid = t >> 5, lane = t & 31;
    const size_t base = (size_t)nh * SEQ * DH;

    for (int i = t; i < SEQ * DH; i += 256) {
        int tt = i >> 5, e = i & 31;
        Ks[tt * 33 + e] = k[base + i];
        Vs[i]           = v[base + i];
    }
    __syncthreads();

    const float scale = 0.17677669529663689f;

    for (int s = wid; s < SEQ; s += 8) {
        float qv = q[base + (size_t)s * DH + lane];
        qs[wid * 32 + lane] = qv;
        __syncwarp();

        float sc[7];
        float mx = -1e30f;
        int cnt = 0;
        for (int t0 = lane; t0 < SEQ; t0 += 32) {
            float acc = 0.f;
#pragma unroll
            for (int e = 0; e < 32; e++) acc += qs[wid * 32 + e] * Ks[t0 * 33 + e];
            acc *= scale;
            sc[cnt++] = acc;
            mx = fmaxf(mx, acc);
        }
#pragma unroll
        for (int off = 16; off; off >>= 1) mx = fmaxf(mx, __shfl_xor_sync(0xffffffffu, mx, off));

        float sum = 0.f;
        cnt = 0;
        for (int t0 = lane; t0 < SEQ; t0 += 32) {
            float p = __expf(sc[cnt++] - mx);
            probs[wid * SEQ + t0] = p;
            sum += p;
        }
#pragma unroll
        for (int off = 16; off; off >>= 1) sum += __shfl_xor_sync(0xffffffffu, sum, off);
        __syncwarp();

        float inv = 1.f / sum;
        float oe = 0.f;
        for (int t0 = 0; t0 < SEQ; t0++) oe += probs[wid * SEQ + t0] * Vs[t0 * 32 + lane];
        o[((size_t)n * SEQ + s) * DMODEL + h * DH + lane] = oe * inv;
        __syncwarp();
    }
}

// ---------------- classification head ---------------------------------------
__global__ void head_kernel(const float* __restrict__ X, const float* __restrict__ w_out,
                            const float* __restrict__ b_out, float* __restrict__ out)
{
    __shared__ float cls_s[DMODEL];
    __shared__ float logits[OUTC];
    __shared__ float red[8];
    const int n = blockIdx.x;
    const int t = threadIdx.x, wid = t >> 5, lane = t & 31;

    cls_s[t] = X[(size_t)n * SEQ * DMODEL + t];
    __syncthreads();

    for (int j = wid; j < OUTC; j += 8) {
        float acc = 0.f;
#pragma unroll
        for (int k = lane; k < DMODEL; k += 32) acc += cls_s[k] * w_out[(size_t)j * DMODEL + k];
#pragma unroll
        for (int off = 16; off; off >>= 1) acc += __shfl_xor_sync(0xffffffffu, acc, off);
        if (lane == 0) logits[j] = acc + b_out[j];
    }
    __syncthreads();

    float mx = -1e30f;
    for (int j = t; j < OUTC; j += 256) mx = fmaxf(mx, logits[j]);
#pragma unroll
    for (int off = 16; off; off >>= 1) mx = fmaxf(mx, __shfl_xor_sync(0xffffffffu, mx, off));
    if (lane == 0) red[wid] = mx;
    __syncthreads();
    float bm = -1e30f;
#pragma unroll
    for (int i = 0; i < 8; i++) bm = fmaxf(bm, red[i]);
    __syncthreads();

    float sum = 0.f;
    for (int j = t; j < OUTC; j += 256) {
        float e = __expf(logits[j] - bm);
        logits[j] = e;
        sum += e;
    }
#pragma unroll
    for (int off = 16; off; off >>= 1) sum += __shfl_xor_sync(0xffffffffu, sum, off);
    if (lane == 0) red[wid] = sum;
    __syncthreads();
    float bs = 0.f;
#pragma unroll
    for (int i = 0; i < 8; i++) bs += red[i];
    float inv = 1.f / bs;
    __syncthreads();
    for (int j = t; j < OUTC; j += 256) out[(size_t)n * OUTC + j] = logits[j] * inv;
}

// ---------------- launcher ----------------
extern "C" void kernel_launch(void* const* d_in, const int* in_sizes, int n_in,
                              void* d_out, int out_size)
{
    const float* images  = (const float*)d_in[0];
    const float* w_map   = (const float*)d_in[1];
    const float* b_map   = (const float*)d_in[2];
    const float* cls_tok = (const float*)d_in[3];
    const float* norm1_g = (const float*)d_in[4];
    const float* norm1_b = (const float*)d_in[5];
    const float* wq      = (const float*)d_in[6];
    const float* bq      = (const float*)d_in[7];
    const float* wk      = (const float*)d_in[8];
    const float* bk      = (const float*)d_in[9];
    const float* wv      = (const float*)d_in[10];
    const float* bv      = (const float*)d_in[11];
    const float* w_last  = (const float*)d_in[12];
    const float* b_last  = (const float*)d_in[13];
    const float* norm2_g = (const float*)d_in[14];
    const float* norm2_b = (const float*)d_in[15];
    const float* w_mlp1  = (const float*)d_in[16];
    const float* b_mlp1  = (const float*)d_in[17];
    const float* w_mlp2  = (const float*)d_in[18];
    const float* b_mlp2  = (const float*)d_in[19];
    const float* w_out   = (const float*)d_in[20];
    const float* b_out   = (const float*)d_in[21];
    float* out = (float*)d_out;

    float *patches, *X, *x1, *qb, *kb, *vb, *ob, *h1, *pe;
    cudaGetSymbolAddress((void**)&patches, g_patches);
    cudaGetSymbolAddress((void**)&X,  g_X);
    cudaGetSymbolAddress((void**)&x1, g_x1);
    cudaGetSymbolAddress((void**)&qb, g_q);
    cudaGetSymbolAddress((void**)&kb, g_k);
    cudaGetSymbolAddress((void**)&vb, g_v);
    cudaGetSymbolAddress((void**)&ob, g_o);
    cudaGetSymbolAddress((void**)&h1, g_h1);
    cudaGetSymbolAddress((void**)&pe, g_pe);

    const int attn_smem = (SEQ * 33 + SEQ * 32 + 8 * SEQ + 8 * 32) * (int)sizeof(float);
    cudaFuncSetAttribute(attn_kernel, cudaFuncAttributeMaxDynamicSharedMemorySize, attn_smem);
    cudaFuncSetAttribute(gemm_tc<0, false>, cudaFuncAttributeMaxDynamicSharedMemorySize, GEMM_SMEM);
    cudaFuncSetAttribute(gemm_tc<0, true >, cudaFuncAttributeMaxDynamicSharedMemorySize, GEMM_SMEM);
    cudaFuncSetAttribute(gemm_tc<1, false>, cudaFuncAttributeMaxDynamicSharedMemorySize, GEMM_SMEM);

    // 1) patches + PE table
    {
        int tot = BATCH * NP * IN_D;
        patch_kernel<<<(tot + 255) / 256, 256>>>(images, patches);
        int pt = SEQ * DMODEL;
        pe_kernel<<<(pt + 255) / 256, 256>>>(pe);
    }

    // 2) patch-embed GEMM: tokens(tmp in h1) = patches @ w_map^T + b_map
    //    M = 25088 (=128*196), N = 256, K = 768
    gemm_tc<0, false><<<dim3(DMODEL / 64, (BATCH * NP) / 128), 256, GEMM_SMEM>>>(
        patches, w_map, b_map, nullptr, h1, BATCH * NP, DMODEL, IN_D);

    // 3) X = concat(cls, tokens) + pe
    {
        int tot = BATCH * SEQ * DMODEL;
        assemble_kernel<<<(tot + 255) / 256, 256>>>(h1, cls_tok, pe, X);
    }

    const int MROWS = BATCH * SEQ;   // 25216 = 128*197

    for (int l = 0; l < NLAYER; l++) {
        layernorm_kernel<<<MROWS, 256>>>(X, norm1_g + l * DMODEL, norm1_b + l * DMODEL, x1);

        qkv_kernel<<<dim3(BATCH * NHEAD, (SEQ + 7) / 8), 256>>>(
            x1,
            wq + (size_t)l * NHEAD * DH * DH, bq + (size_t)l * NHEAD * DH,
            wk + (size_t)l * NHEAD * DH * DH, bk + (size_t)l * NHEAD * DH,
            wv + (size_t)l * NHEAD * DH * DH, bv + (size_t)l * NHEAD * DH,
            qb, kb, vb);

        attn_kernel<<<BATCH * NHEAD, 256, attn_smem>>>(qb, kb, vb, ob);

        // o-proj + residual: X = X + o @ w_last^T + b_last (25216,256,256)
        gemm_tc<0, true><<<dim3(DMODEL / 64, MROWS / 128), 256, GEMM_SMEM>>>(
            ob, w_last + (size_t)l * DMODEL * DMODEL, b_last + l * DMODEL, X, X,
            MROWS, DMODEL, DMODEL);

        layernorm_kernel<<<MROWS, 256>>>(X, norm2_g + l * DMODEL, norm2_b + l * DMODEL, x1);

        // MLP1 + GELU: h1 = gelu(x2 @ w_mlp1^T + b1) (25216,1024,256)
        gemm_tc<1, false><<<dim3((4 * DMODEL) / 64, MROWS / 128), 256, GEMM_SMEM>>>(
            x1, w_mlp1 + (size_t)l * 4 * DMODEL * DMODEL, b_mlp1 + l * 4 * DMODEL,
            nullptr, h1, MROWS, 4 * DMODEL, DMODEL);

        // MLP2 + residual: X = X + h1 @ w_mlp2^T + b2 (25216,256,1024)
        gemm_tc<0, true><<<dim3(DMODEL / 64, MROWS / 128), 256, GEMM_SMEM>>>(
            h1, w_mlp2 + (size_t)l * 4 * DMODEL * DMODEL, b_mlp2 + l * DMODEL, X, X,
            MROWS, DMODEL, 4 * DMODEL);
    }

    head_kernel<<<BATCH, 256>>>(X, w_out, b_out, out);
}

// round 3
// speedup vs baseline: 2.1588x; 1.3871x over previous
#include <cuda_runtime.h>
#include <cuda_bf16.h>
#include <math.h>
#include <stdint.h>

// ---------------- problem constants ----------------
#define BATCH 128
#define CH    3
#define HIM   224
#define PGRID 14
#define NP    196
#define PATCH 16
#define IN_D  768
#define DMODEL 256
#define NHEAD 8
#define DH    32
#define NLAYER 4
#define SEQ   197
#define OUTC  1000
#define LNEPS 1e-5f

typedef __nv_bfloat16 bf16;

// ---------------- scratch (device globals) ----------------
__device__ bf16  g_patches_b[BATCH * NP * IN_D];          // 38.5 MB
__device__ float g_tok[BATCH * NP * DMODEL];              // 25.7 MB
__device__ float g_X [BATCH * SEQ * DMODEL];              // 25.8 MB
__device__ bf16  g_x1b[BATCH * SEQ * DMODEL];
__device__ bf16  g_qb [BATCH * SEQ * DMODEL];             // [n,h,s,e]
__device__ bf16  g_kb [BATCH * SEQ * DMODEL];
__device__ bf16  g_vb [BATCH * SEQ * DMODEL];
__device__ bf16  g_ob [BATCH * SEQ * DMODEL];             // [n,s,d]
__device__ bf16  g_h1b[BATCH * SEQ * 4 * DMODEL];         // 51.6 MB
__device__ float g_pe[SEQ * DMODEL];
__device__ bf16  g_wmapb [DMODEL * IN_D];
__device__ bf16  g_wlastb[NLAYER * DMODEL * DMODEL];
__device__ bf16  g_wmlp1b[NLAYER * 4 * DMODEL * DMODEL];
__device__ bf16  g_wmlp2b[NLAYER * 4 * DMODEL * DMODEL];

// ---------------- fp32 -> bf16 convert ----------------
__global__ void cvt_kernel(const float* __restrict__ src, bf16* __restrict__ dst, int n)
{
    int i = (blockIdx.x * 256 + threadIdx.x) * 4;
    if (i >= n) return;
    float4 v = *(const float4*)(src + i);
    __nv_bfloat162 p0 = __floats2bfloat162_rn(v.x, v.y);
    __nv_bfloat162 p1 = __floats2bfloat162_rn(v.z, v.w);
    uint2 o;
    o.x = *reinterpret_cast<uint32_t*>(&p0);
    o.y = *reinterpret_cast<uint32_t*>(&p1);
    *reinterpret_cast<uint2*>(dst + i) = o;
}

// ---------------- patch extraction (writes bf16) ----------------
__global__ void patch_kernel(const float* __restrict__ img, bf16* __restrict__ out)
{
    int idx = blockIdx.x * 256 + threadIdx.x;
    if (idx >= BATCH * NP * IN_D) return;
    int i = idx % IN_D;
    int p = (idx / IN_D) % NP;
    int n = idx / (IN_D * NP);
    int c   = i >> 8;
    int r   = (i >> 4) & 15;
    int col = i & 15;
    int py = p / PGRID, px = p % PGRID;
    out[idx] = __float2bfloat16(
        img[(((size_t)n * CH + c) * HIM + py * PATCH + r) * HIM + px * PATCH + col]);
}

// ---------------- positional encoding (fp64) ----------------
__global__ void pe_kernel(float* __restrict__ pe)
{
    int i = blockIdx.x * 256 + threadIdx.x;
    if (i >= SEQ * DMODEL) return;
    int s = i / DMODEL, d = i % DMODEL;
    double expo = (double)(2 * (d / 2)) / (double)DMODEL;
    double ang  = (double)s / pow(10000.0, expo);
    pe[i] = (float)((d & 1) ? cos(ang) : sin(ang));
}

// ---------------- assemble X = concat(cls, tokens) + pe --------------------
__global__ void assemble_kernel(const float* __restrict__ tok,
                                const float* __restrict__ cls,
                                const float* __restrict__ pe,
                                float* __restrict__ X)
{
    int i = blockIdx.x * 256 + threadIdx.x;
    if (i >= BATCH * SEQ * DMODEL) return;
    int d = i % DMODEL;
    int s = (i / DMODEL) % SEQ;
    int n = i / (SEQ * DMODEL);
    float v = (s == 0) ? cls[d]
                       : tok[((size_t)n * NP + (s - 1)) * DMODEL + d];
    X[i] = v + pe[s * DMODEL + d];
}

// ---------------- bf16 tensor-core GEMM -------------------------------------
// C = act(A @ W^T + bias) (+res). A:[M,K] bf16 row-major, W:[N,K] bf16 row-major.
// Block tile 128x64, K-tile 64, 8 warps, cp.async double-buffered SMEM.
// Requires M%128==0, N%64==0, K%64==0.
__device__ __forceinline__ void mma_bf16(float* c, const uint32_t* a, const uint32_t* b)
{
    asm volatile(
        "mma.sync.aligned.m16n8k16.row.col.f32.bf16.bf16.f32 "
        "{%0,%1,%2,%3}, {%4,%5,%6,%7}, {%8,%9}, {%0,%1,%2,%3};"
        : "+f"(c[0]), "+f"(c[1]), "+f"(c[2]), "+f"(c[3])
        : "r"(a[0]), "r"(a[1]), "r"(a[2]), "r"(a[3]), "r"(b[0]), "r"(b[1]));
}

#define CP16(dst, src) asm volatile("cp.async.cg.shared.global [%0], [%1], 16;\n" :: "r"(dst), "l"(src))
#define CP_COMMIT()    asm volatile("cp.async.commit_group;\n" ::)
#define CP_WAIT1()     asm volatile("cp.async.wait_group 1;\n" ::)
#define CP_WAIT0()     asm volatile("cp.async.wait_group 0;\n" ::)

#define STR 36                      // u32 stride per 64-bf16 row (pad 4)
#define A_BUF (128 * STR)           // u32
#define B_BUF (64 * STR)            // u32
#define GEMM_SMEM ((2 * A_BUF + 2 * B_BUF) * 4)

template<int ACT, bool HASRES, bool OUTBF>
__global__ void __launch_bounds__(256) gemm_bf(const bf16* __restrict__ A,
                                               const bf16* __restrict__ W,
                                               const float* __restrict__ bias,
                                               const float* __restrict__ res,
                                               void* __restrict__ Cout,
                                               int M, int N, int K)
{
    extern __shared__ uint32_t sm_[];
    const uint32_t smem_byte = (uint32_t)__cvta_generic_to_shared(sm_);

    const int t    = threadIdx.x;
    const int warp = t >> 5, lane = t & 31;
    const int g    = lane >> 2, q4 = lane & 3;
    const int warp_m = (warp >> 1) * 32;
    const int warp_n = (warp & 1) * 32;
    const int row0 = blockIdx.y * 128, col0 = blockIdx.x * 64;

    float acc[2][4][4];
#pragma unroll
    for (int mi = 0; mi < 2; mi++)
#pragma unroll
        for (int ni = 0; ni < 4; ni++)
#pragma unroll
            for (int e = 0; e < 4; e++) acc[mi][ni][e] = 0.f;

    auto stage = [&](int k0, int buf) {
        uint32_t abase = smem_byte + buf * (A_BUF * 4);
#pragma unroll
        for (int i = 0; i < 4; i++) {
            int c = t + i * 256;
            int r = c >> 3, co = c & 7;
            uint32_t dst = abase + (r * STR + co * 4) * 4;
            const bf16* src = A + (size_t)(row0 + r) * K + k0 + co * 8;
            CP16(dst, src);
        }
        uint32_t bbase = smem_byte + (2 * A_BUF + buf * B_BUF) * 4;
#pragma unroll
        for (int i = 0; i < 2; i++) {
            int c = t + i * 256;
            int r = c >> 3, co = c & 7;
            uint32_t dst = bbase + (r * STR + co * 4) * 4;
            const bf16* src = W + (size_t)(col0 + r) * K + k0 + co * 8;
            CP16(dst, src);
        }
        CP_COMMIT();
    };

    const int KT = K >> 6;
    stage(0, 0);

    for (int kt = 0; kt < KT; kt++) {
        const int cur = kt & 1;
        if (kt + 1 < KT) { stage((kt + 1) << 6, cur ^ 1); CP_WAIT1(); }
        else             { CP_WAIT0(); }
        __syncthreads();

        const uint32_t* Ab = sm_ + cur * A_BUF;
        const uint32_t* Bb = sm_ + 2 * A_BUF + cur * B_BUF;
#pragma unroll
        for (int ks = 0; ks < 4; ks++) {
            const int ko = ks << 3;
            uint32_t af[2][4];
#pragma unroll
            for (int mi = 0; mi < 2; mi++) {
                int r = warp_m + mi * 16 + g;
                af[mi][0] = Ab[r * STR + ko + q4];
                af[mi][1] = Ab[(r + 8) * STR + ko + q4];
                af[mi][2] = Ab[r * STR + ko + q4 + 4];
                af[mi][3] = Ab[(r + 8) * STR + ko + q4 + 4];
            }
            uint32_t bf_[4][2];
#pragma unroll
            for (int ni = 0; ni < 4; ni++) {
                int n = warp_n + ni * 8 + g;
                bf_[ni][0] = Bb[n * STR + ko + q4];
                bf_[ni][1] = Bb[n * STR + ko + q4 + 4];
            }
#pragma unroll
            for (int mi = 0; mi < 2; mi++)
#pragma unroll
                for (int ni = 0; ni < 4; ni++)
                    mma_bf16(acc[mi][ni], af[mi], bf_[ni]);
        }
        __syncthreads();
    }

    // epilogue: bias (+gelu) (+residual); out fp32 or bf16
#pragma unroll
    for (int mi = 0; mi < 2; mi++) {
        int ra = row0 + warp_m + mi * 16 + g;
        int rb = ra + 8;
#pragma unroll
        for (int ni = 0; ni < 4; ni++) {
            int col = col0 + warp_n + ni * 8 + q4 * 2;
            float b0 = bias[col], b1 = bias[col + 1];
            float v00 = acc[mi][ni][0] + b0, v01 = acc[mi][ni][1] + b1;
            float v10 = acc[mi][ni][2] + b0, v11 = acc[mi][ni][3] + b1;
            if (ACT == 1) {
                v00 = 0.5f * v00 * (1.0f + erff(v00 * 0.70710678118654752f));
                v01 = 0.5f * v01 * (1.0f + erff(v01 * 0.70710678118654752f));
                v10 = 0.5f * v10 * (1.0f + erff(v10 * 0.70710678118654752f));
                v11 = 0.5f * v11 * (1.0f + erff(v11 * 0.70710678118654752f));
            }
            if (HASRES) {
                float2 r0 = *(const float2*)(res + (size_t)ra * N + col);
                float2 r1 = *(const float2*)(res + (size_t)rb * N + col);
                v00 += r0.x; v01 += r0.y; v10 += r1.x; v11 += r1.y;
            }
            if (OUTBF) {
                bf16* C = (bf16*)Cout;
                __nv_bfloat162 p0 = __floats2bfloat162_rn(v00, v01);
                __nv_bfloat162 p1 = __floats2bfloat162_rn(v10, v11);
                *reinterpret_cast<uint32_t*>(C + (size_t)ra * N + col) = *reinterpret_cast<uint32_t*>(&p0);
                *reinterpret_cast<uint32_t*>(C + (size_t)rb * N + col) = *reinterpret_cast<uint32_t*>(&p1);
            } else {
                float* C = (float*)Cout;
                *(float2*)(C + (size_t)ra * N + col) = make_float2(v00, v01);
                *(float2*)(C + (size_t)rb * N + col) = make_float2(v10, v11);
            }
        }
    }
}

// ---------------- LayerNorm: warp per row, bf16 out -------------------------
__global__ void ln_kernel(const float* __restrict__ x,
                          const float* __restrict__ g,
                          const float* __restrict__ b,
                          bf16* __restrict__ y)
{
    const int row  = blockIdx.x * 8 + (threadIdx.x >> 5);
    const int lane = threadIdx.x & 31;
    const float4* xp = (const float4*)(x + (size_t)row * DMODEL);
    float4 u = xp[lane * 2], w = xp[lane * 2 + 1];

    float s = u.x + u.y + u.z + u.w + w.x + w.y + w.z + w.w;
#pragma unroll
    for (int off = 16; off; off >>= 1) s += __shfl_xor_sync(0xffffffffu, s, off);
    float mu = s * (1.f / DMODEL);

    float d0 = u.x - mu, d1 = u.y - mu, d2 = u.z - mu, d3 = u.w - mu;
    float d4 = w.x - mu, d5 = w.y - mu, d6 = w.z - mu, d7 = w.w - mu;
    float s2 = d0*d0 + d1*d1 + d2*d2 + d3*d3 + d4*d4 + d5*d5 + d6*d6 + d7*d7;
#pragma unroll
    for (int off = 16; off; off >>= 1) s2 += __shfl_xor_sync(0xffffffffu, s2, off);
    float inv = rsqrtf(s2 * (1.f / DMODEL) + LNEPS);

    const float4* gp = (const float4*)g;
    const float4* bp = (const float4*)b;
    float4 g0 = gp[lane * 2], g1 = gp[lane * 2 + 1];
    float4 b0 = bp[lane * 2], b1 = bp[lane * 2 + 1];

    __nv_bfloat162 p0 = __floats2bfloat162_rn(d0 * inv * g0.x + b0.x, d1 * inv * g0.y + b0.y);
    __nv_bfloat162 p1 = __floats2bfloat162_rn(d2 * inv * g0.z + b0.z, d3 * inv * g0.w + b0.w);
    __nv_bfloat162 p2 = __floats2bfloat162_rn(d4 * inv * g1.x + b1.x, d5 * inv * g1.y + b1.y);
    __nv_bfloat162 p3 = __floats2bfloat162_rn(d6 * inv * g1.z + b1.z, d7 * inv * g1.w + b1.w);
    uint4 o;
    o.x = *reinterpret_cast<uint32_t*>(&p0);
    o.y = *reinterpret_cast<uint32_t*>(&p1);
    o.z = *reinterpret_cast<uint32_t*>(&p2);
    o.w = *reinterpret_cast<uint32_t*>(&p3);
    *reinterpret_cast<uint4*>(y + (size_t)row * DMODEL + lane * 8) = o;
}

// ---------------- fused per-head QKV projection (bf16 io) -------------------
__global__ void qkv_kernel(const bf16* __restrict__ x1,
                           const float* __restrict__ wq, const float* __restrict__ bq,
                           const float* __restrict__ wk, const float* __restrict__ bk,
                           const float* __restrict__ wv, const float* __restrict__ bv,
                           bf16* __restrict__ q, bf16* __restrict__ k, bf16* __restrict__ v)
{
    __shared__ float wqs[32 * 33], wks[32 * 33], wvs[32 * 33];
    __shared__ float bqs[32], bks[32], bvs[32];
    __shared__ float xr[8][32];
    const int nh = blockIdx.x;
    const int n = nh / NHEAD, h = nh % NHEAD;
    const int t = threadIdx.x;
    const float* wqg = wq + (size_t)h * DH * DH;
    const float* wkg = wk + (size_t)h * DH * DH;
    const float* wvg = wv + (size_t)h * DH * DH;

    for (int i = t; i < DH * DH; i += 256) {
        int e = i >> 5, d = i & 31;
        wqs[e * 33 + d] = wqg[i];
        wks[e * 33 + d] = wkg[i];
        wvs[e * 33 + d] = wvg[i];
    }
    if (t < 32) { bqs[t] = bq[h * DH + t]; bks[t] = bk[h * DH + t]; bvs[t] = bv[h * DH + t]; }

    const int sl = t >> 5, lane = t & 31;
    const int s = blockIdx.y * 8 + sl;
    if (s < SEQ) xr[sl][lane] = __bfloat162float(x1[((size_t)n * SEQ + s) * DMODEL + h * DH + lane]);
    __syncthreads();
    if (s >= SEQ) return;

    float aq = bqs[lane], ak = bks[lane], av = bvs[lane];
#pragma unroll
    for (int d = 0; d < 32; d++) {
        float xv = xr[sl][d];
        aq += xv * wqs[lane * 33 + d];
        ak += xv * wks[lane * 33 + d];
        av += xv * wvs[lane * 33 + d];
    }
    size_t oidx = ((size_t)nh * SEQ + s) * DH + lane;
    q[oidx] = __float2bfloat16(aq);
    k[oidx] = __float2bfloat16(ak);
    v[oidx] = __float2bfloat16(av);
}

// ---------------- fused attention per (n,h) ---------------------------------
__global__ void attn_kernel(const bf16* __restrict__ q, const bf16* __restrict__ k,
                            const bf16* __restrict__ v, bf16* __restrict__ o)
{
    extern __shared__ float sm[];
    float* Ks    = sm;
    float* Vs    = Ks + SEQ * 33;
    float* probs = Vs + SEQ * 32;
    float* qs    = probs + 8 * SEQ;

    const int nh = blockIdx.x;
    const int n = nh / NHEAD, h = nh % NHEAD;
    const int t = threadIdx.x, wid = t >> 5, lane = t & 31;
    const size_t base = (size_t)nh * SEQ * DH;

    for (int i = t; i < SEQ * DH; i += 256) {
        int tt = i >> 5, e = i & 31;
        Ks[tt * 33 + e] = __bfloat162float(k[base + i]);
        Vs[i]           = __bfloat162float(v[base + i]);
    }
    __syncthreads();

    const float scale = 0.17677669529663689f;

    for (int s = wid; s < SEQ; s += 8) {
        qs[wid * 32 + lane] = __bfloat162float(q[base + (size_t)s * DH + lane]);
        __syncwarp();

        float sc[7];
        float mx = -1e30f;
        int cnt = 0;
        for (int t0 = lane; t0 < SEQ; t0 += 32) {
            float acc = 0.f;
#pragma unroll
            for (int e = 0; e < 32; e++) acc += qs[wid * 32 + e] * Ks[t0 * 33 + e];
            acc *= scale;
            sc[cnt++] = acc;
            mx = fmaxf(mx, acc);
        }
#pragma unroll
        for (int off = 16; off; off >>= 1) mx = fmaxf(mx, __shfl_xor_sync(0xffffffffu, mx, off));

        float sum = 0.f;
        cnt = 0;
        for (int t0 = lane; t0 < SEQ; t0 += 32) {
            float p = __expf(sc[cnt++] - mx);
            probs[wid * SEQ + t0] = p;
            sum += p;
        }
#pragma unroll
        for (int off = 16; off; off >>= 1) sum += __shfl_xor_sync(0xffffffffu, sum, off);
        __syncwarp();

        float inv = 1.f / sum;
        float oe = 0.f;
#pragma unroll 4
        for (int t0 = 0; t0 < SEQ; t0++) oe += probs[wid * SEQ + t0] * Vs[t0 * 32 + lane];
        o[((size_t)n * SEQ + s) * DMODEL + h * DH + lane] = __float2bfloat16(oe * inv);
        __syncwarp();
    }
}

// ---------------- classification head ---------------------------------------
__global__ void head_kernel(const float* __restrict__ X, const float* __restrict__ w_out,
                            const float* __restrict__ b_out, float* __restrict__ out)
{
    __shared__ float cls_s[DMODEL];
    __shared__ float logits[OUTC];
    __shared__ float red[8];
    const int n = blockIdx.x;
    const int t = threadIdx.x, wid = t >> 5, lane = t & 31;

    cls_s[t] = X[(size_t)n * SEQ * DMODEL + t];
    __syncthreads();

    for (int j = wid; j < OUTC; j += 8) {
        float acc = 0.f;
#pragma unroll
        for (int k = lane; k < DMODEL; k += 32) acc += cls_s[k] * w_out[(size_t)j * DMODEL + k];
#pragma unroll
        for (int off = 16; off; off >>= 1) acc += __shfl_xor_sync(0xffffffffu, acc, off);
        if (lane == 0) logits[j] = acc + b_out[j];
    }
    __syncthreads();

    float mx = -1e30f;
    for (int j = t; j < OUTC; j += 256) mx = fmaxf(mx, logits[j]);
#pragma unroll
    for (int off = 16; off; off >>= 1) mx = fmaxf(mx, __shfl_xor_sync(0xffffffffu, mx, off));
    if (lane == 0) red[wid] = mx;
    __syncthreads();
    float bm = -1e30f;
#pragma unroll
    for (int i = 0; i < 8; i++) bm = fmaxf(bm, red[i]);
    __syncthreads();

    float sum = 0.f;
    for (int j = t; j < OUTC; j += 256) {
        float e = __expf(logits[j] - bm);
        logits[j] = e;
        sum += e;
    }
#pragma unroll
    for (int off = 16; off; off >>= 1) sum += __shfl_xor_sync(0xffffffffu, sum, off);
    if (lane == 0) red[wid] = sum;
    __syncthreads();
    float bs = 0.f;
#pragma unroll
    for (int i = 0; i < 8; i++) bs += red[i];
    float inv = 1.f / bs;
    __syncthreads();
    for (int j = t; j < OUTC; j += 256) out[(size_t)n * OUTC + j] = logits[j] * inv;
}

// ---------------- launcher ----------------
extern "C" void kernel_launch(void* const* d_in, const int* in_sizes, int n_in,
                              void* d_out, int out_size)
{
    const float* images  = (const float*)d_in[0];
    const float* w_map   = (const float*)d_in[1];
    const float* b_map   = (const float*)d_in[2];
    const float* cls_tok = (const float*)d_in[3];
    const float* norm1_g = (const float*)d_in[4];
    const float* norm1_b = (const float*)d_in[5];
    const float* wq      = (const float*)d_in[6];
    const float* bq      = (const float*)d_in[7];
    const float* wk      = (const float*)d_in[8];
    const float* bk      = (const float*)d_in[9];
    const float* wv      = (const float*)d_in[10];
    const float* bv      = (const float*)d_in[11];
    const float* w_last  = (const float*)d_in[12];
    const float* b_last  = (const float*)d_in[13];
    const float* norm2_g = (const float*)d_in[14];
    const float* norm2_b = (const float*)d_in[15];
    const float* w_mlp1  = (const float*)d_in[16];
    const float* b_mlp1  = (const float*)d_in[17];
    const float* w_mlp2  = (const float*)d_in[18];
    const float* b_mlp2  = (const float*)d_in[19];
    const float* w_out   = (const float*)d_in[20];
    const float* b_out   = (const float*)d_in[21];
    float* out = (float*)d_out;

    bf16 *patches, *x1b, *qb, *kb, *vb, *ob, *h1b, *wmapb, *wlastb, *wmlp1b, *wmlp2b;
    float *X, *tok, *pe;
    cudaGetSymbolAddress((void**)&patches, g_patches_b);
    cudaGetSymbolAddress((void**)&tok, g_tok);
    cudaGetSymbolAddress((void**)&X,   g_X);
    cudaGetSymbolAddress((void**)&x1b, g_x1b);
    cudaGetSymbolAddress((void**)&qb,  g_qb);
    cudaGetSymbolAddress((void**)&kb,  g_kb);
    cudaGetSymbolAddress((void**)&vb,  g_vb);
    cudaGetSymbolAddress((void**)&ob,  g_ob);
    cudaGetSymbolAddress((void**)&h1b, g_h1b);
    cudaGetSymbolAddress((void**)&pe,  g_pe);
    cudaGetSymbolAddress((void**)&wmapb,  g_wmapb);
    cudaGetSymbolAddress((void**)&wlastb, g_wlastb);
    cudaGetSymbolAddress((void**)&wmlp1b, g_wmlp1b);
    cudaGetSymbolAddress((void**)&wmlp2b, g_wmlp2b);

    const int attn_smem = (SEQ * 33 + SEQ * 32 + 8 * SEQ + 8 * 32) * (int)sizeof(float);
    cudaFuncSetAttribute(attn_kernel, cudaFuncAttributeMaxDynamicSharedMemorySize, attn_smem);
    cudaFuncSetAttribute(gemm_bf<0, false, false>, cudaFuncAttributeMaxDynamicSharedMemorySize, GEMM_SMEM);
    cudaFuncSetAttribute(gemm_bf<0, true,  false>, cudaFuncAttributeMaxDynamicSharedMemorySize, GEMM_SMEM);
    cudaFuncSetAttribute(gemm_bf<1, false, true >, cudaFuncAttributeMaxDynamicSharedMemorySize, GEMM_SMEM);

    // 0) weight conversion to bf16
    {
        int n1 = DMODEL * IN_D;
        cvt_kernel<<<(n1 / 4 + 255) / 256, 256>>>(w_map, wmapb, n1);
        int n2 = NLAYER * DMODEL * DMODEL;
        cvt_kernel<<<(n2 / 4 + 255) / 256, 256>>>(w_last, wlastb, n2);
        int n3 = NLAYER * 4 * DMODEL * DMODEL;
        cvt_kernel<<<(n3 / 4 + 255) / 256, 256>>>(w_mlp1, wmlp1b, n3);
        cvt_kernel<<<(n3 / 4 + 255) / 256, 256>>>(w_mlp2, wmlp2b, n3);
    }

    // 1) patches + PE table
    {
        int tot = BATCH * NP * IN_D;
        patch_kernel<<<(tot + 255) / 256, 256>>>(images, patches);
        int pt = SEQ * DMODEL;
        pe_kernel<<<(pt + 255) / 256, 256>>>(pe);
    }

    // 2) patch-embed GEMM: tok = patches @ w_map^T + b_map  (25088, 256, 768)
    gemm_bf<0, false, false><<<dim3(DMODEL / 64, (BATCH * NP) / 128), 256, GEMM_SMEM>>>(
        patches, wmapb, b_map, nullptr, tok, BATCH * NP, DMODEL, IN_D);

    // 3) X = concat(cls, tok) + pe
    {
        int tot = BATCH * SEQ * DMODEL;
        assemble_kernel<<<(tot + 255) / 256, 256>>>(tok, cls_tok, pe, X);
    }

    const int MROWS = BATCH * SEQ;   // 25216 = 128*197

    for (int l = 0; l < NLAYER; l++) {
        ln_kernel<<<MROWS / 8, 256>>>(X, norm1_g + l * DMODEL, norm1_b + l * DMODEL, x1b);

        qkv_kernel<<<dim3(BATCH * NHEAD, (SEQ + 7) / 8), 256>>>(
            x1b,
            wq + (size_t)l * NHEAD * DH * DH, bq + (size_t)l * NHEAD * DH,
            wk + (size_t)l * NHEAD * DH * DH, bk + (size_t)l * NHEAD * DH,
            wv + (size_t)l * NHEAD * DH * DH, bv + (size_t)l * NHEAD * DH,
            qb, kb, vb);

        attn_kernel<<<BATCH * NHEAD, 256, attn_smem>>>(qb, kb, vb, ob);

        // o-proj + residual: X = X + o @ w_last^T + b_last (25216,256,256)
        gemm_bf<0, true, false><<<dim3(DMODEL / 64, MROWS / 128), 256, GEMM_SMEM>>>(
            ob, wlastb + (size_t)l * DMODEL * DMODEL, b_last + l * DMODEL, X, X,
            MROWS, DMODEL, DMODEL);

        ln_kernel<<<MROWS / 8, 256>>>(X, norm2_g + l * DMODEL, norm2_b + l * DMODEL, x1b);

        // MLP1 + GELU -> bf16 h1 (25216,1024,256)
        gemm_bf<1, false, true><<<dim3((4 * DMODEL) / 64, MROWS / 128), 256, GEMM_SMEM>>>(
            x1b, wmlp1b + (size_t)l * 4 * DMODEL * DMODEL, b_mlp1 + l * 4 * DMODEL,
            nullptr, h1b, MROWS, 4 * DMODEL, DMODEL);

        // MLP2 + residual: X = X + h1 @ w_mlp2^T + b2 (25216,256,1024)
        gemm_bf<0, true, false><<<dim3(DMODEL / 64, MROWS / 128), 256, GEMM_SMEM>>>(
            h1b, wmlp2b + (size_t)l * 4 * DMODEL * DMODEL, b_mlp2 + l * DMODEL, X, X,
            MROWS, DMODEL, 4 * DMODEL);
    }

    head_kernel<<<BATCH, 256>>>(X, w_out, b_out, out);
}

// round 4
// speedup vs baseline: 4.2886x; 1.9866x over previous
#include <cuda_runtime.h>
#include <cuda_bf16.h>
#include <math.h>
#include <stdint.h>

// ---------------- problem constants ----------------
#define BATCH 128
#define CH    3
#define HIM   224
#define PGRID 14
#define NP    196
#define PATCH 16
#define IN_D  768
#define DMODEL 256
#define NHEAD 8
#define DH    32
#define NLAYER 4
#define SEQ   197
#define OUTC  1000
#define LNEPS 1e-5f

typedef __nv_bfloat16 bf16;

// ---------------- scratch (device globals) ----------------
__device__ bf16  g_patches_b[BATCH * NP * IN_D];
__device__ float g_tok[BATCH * NP * DMODEL];
__device__ float g_X [BATCH * SEQ * DMODEL];
__device__ bf16  g_x1b[BATCH * SEQ * DMODEL];
__device__ bf16  g_qb [BATCH * SEQ * DMODEL];             // [n,h,s,e]
__device__ bf16  g_kb [BATCH * SEQ * DMODEL];
__device__ bf16  g_vb [BATCH * SEQ * DMODEL];
__device__ bf16  g_ob [BATCH * SEQ * DMODEL];             // [n,s,d]
__device__ bf16  g_h1b[BATCH * SEQ * 4 * DMODEL];
__device__ float g_pe[SEQ * DMODEL];
__device__ bf16  g_wmapb [DMODEL * IN_D];
__device__ bf16  g_wlastb[NLAYER * DMODEL * DMODEL];
__device__ bf16  g_wmlp1b[NLAYER * 4 * DMODEL * DMODEL];
__device__ bf16  g_wmlp2b[NLAYER * 4 * DMODEL * DMODEL];

// ---------------- fp32 -> bf16 convert ----------------
__global__ void cvt_kernel(const float* __restrict__ src, bf16* __restrict__ dst, int n)
{
    int i = (blockIdx.x * 256 + threadIdx.x) * 4;
    if (i >= n) return;
    float4 v = *(const float4*)(src + i);
    __nv_bfloat162 p0 = __floats2bfloat162_rn(v.x, v.y);
    __nv_bfloat162 p1 = __floats2bfloat162_rn(v.z, v.w);
    uint2 o;
    o.x = *reinterpret_cast<uint32_t*>(&p0);
    o.y = *reinterpret_cast<uint32_t*>(&p1);
    *reinterpret_cast<uint2*>(dst + i) = o;
}

// ---------------- patch extraction (writes bf16) ----------------
__global__ void patch_kernel(const float* __restrict__ img, bf16* __restrict__ out)
{
    int idx = blockIdx.x * 256 + threadIdx.x;
    if (idx >= BATCH * NP * IN_D) return;
    int i = idx % IN_D;
    int p = (idx / IN_D) % NP;
    int n = idx / (IN_D * NP);
    int c   = i >> 8;
    int r   = (i >> 4) & 15;
    int col = i & 15;
    int py = p / PGRID, px = p % PGRID;
    out[idx] = __float2bfloat16(
        img[(((size_t)n * CH + c) * HIM + py * PATCH + r) * HIM + px * PATCH + col]);
}

// ---------------- positional encoding (fp64) ----------------
__global__ void pe_kernel(float* __restrict__ pe)
{
    int i = blockIdx.x * 256 + threadIdx.x;
    if (i >= SEQ * DMODEL) return;
    int s = i / DMODEL, d = i % DMODEL;
    double expo = (double)(2 * (d / 2)) / (double)DMODEL;
    double ang  = (double)s / pow(10000.0, expo);
    pe[i] = (float)((d & 1) ? cos(ang) : sin(ang));
}

// ---------------- assemble X = concat(cls, tokens) + pe --------------------
__global__ void assemble_kernel(const float* __restrict__ tok,
                                const float* __restrict__ cls,
                                const float* __restrict__ pe,
                                float* __restrict__ X)
{
    int i = blockIdx.x * 256 + threadIdx.x;
    if (i >= BATCH * SEQ * DMODEL) return;
    int d = i % DMODEL;
    int s = (i / DMODEL) % SEQ;
    int n = i / (SEQ * DMODEL);
    float v = (s == 0) ? cls[d]
                       : tok[((size_t)n * NP + (s - 1)) * DMODEL + d];
    X[i] = v + pe[s * DMODEL + d];
}

// ---------------- bf16 MMA helper -------------------------------------------
__device__ __forceinline__ void mma_bf16(float* c, const uint32_t* a, const uint32_t* b)
{
    asm volatile(
        "mma.sync.aligned.m16n8k16.row.col.f32.bf16.bf16.f32 "
        "{%0,%1,%2,%3}, {%4,%5,%6,%7}, {%8,%9}, {%0,%1,%2,%3};"
        : "+f"(c[0]), "+f"(c[1]), "+f"(c[2]), "+f"(c[3])
        : "r"(a[0]), "r"(a[1]), "r"(a[2]), "r"(a[3]), "r"(b[0]), "r"(b[1]));
}

#define CP16(dst, src) asm volatile("cp.async.cg.shared.global [%0], [%1], 16;\n" :: "r"(dst), "l"(src))
#define CP_COMMIT()    asm volatile("cp.async.commit_group;\n" ::)
#define CP_WAIT1()     asm volatile("cp.async.wait_group 1;\n" ::)
#define CP_WAIT0()     asm volatile("cp.async.wait_group 0;\n" ::)

// ---------------- bf16 tensor-core GEMM, 128x128 tile ----------------------
// C = act(A @ W^T + bias) (+res). A:[M,K] bf16, W:[N,K] bf16, both row-major.
// K-tile 64, 8 warps (4m x 2n, 32x64 each), cp.async double buffer.
// Requires M%128==0, N%128==0, K%64==0.
#define STR 36                      // u32 stride per 64-bf16 row (pad 4)
#define ABUF (128 * STR)            // u32
#define GEMM_SMEM (4 * ABUF * 4)    // A0,A1,B0,B1

template<int ACT, bool HASRES, bool OUTBF>
__global__ void __launch_bounds__(256) gemm_bf(const bf16* __restrict__ A,
                                               const bf16* __restrict__ W,
                                               const float* __restrict__ bias,
                                               const float* __restrict__ res,
                                               void* __restrict__ Cout,
                                               int M, int N, int K)
{
    extern __shared__ uint32_t sm_[];
    const uint32_t smem_byte = (uint32_t)__cvta_generic_to_shared(sm_);

    const int t    = threadIdx.x;
    const int warp = t >> 5, lane = t & 31;
    const int g    = lane >> 2, q4 = lane & 3;
    const int warp_m = (warp >> 1) * 32;
    const int warp_n = (warp & 1) * 64;
    const int row0 = blockIdx.y * 128, col0 = blockIdx.x * 128;

    float acc[2][8][4];
#pragma unroll
    for (int mi = 0; mi < 2; mi++)
#pragma unroll
        for (int ni = 0; ni < 8; ni++)
#pragma unroll
            for (int e = 0; e < 4; e++) acc[mi][ni][e] = 0.f;

    auto stage = [&](int k0, int buf) {
        uint32_t abase = smem_byte + buf * (ABUF * 4);
        uint32_t bbase = smem_byte + (2 + buf) * (ABUF * 4);
#pragma unroll
        for (int i = 0; i < 4; i++) {
            int c = t + i * 256;
            int r = c >> 3, co = c & 7;
            CP16(abase + (r * STR + co * 4) * 4, A + (size_t)(row0 + r) * K + k0 + co * 8);
            CP16(bbase + (r * STR + co * 4) * 4, W + (size_t)(col0 + r) * K + k0 + co * 8);
        }
        CP_COMMIT();
    };

    const int KT = K >> 6;
    stage(0, 0);

    for (int kt = 0; kt < KT; kt++) {
        const int cur = kt & 1;
        if (kt + 1 < KT) { stage((kt + 1) << 6, cur ^ 1); CP_WAIT1(); }
        else             { CP_WAIT0(); }
        __syncthreads();

        const uint32_t* Ab = sm_ + cur * ABUF;
        const uint32_t* Bb = sm_ + (2 + cur) * ABUF;
#pragma unroll
        for (int ks = 0; ks < 4; ks++) {
            const int ko = ks << 3;
            uint32_t af[2][4];
#pragma unroll
            for (int mi = 0; mi < 2; mi++) {
                int r = warp_m + mi * 16 + g;
                af[mi][0] = Ab[r * STR + ko + q4];
                af[mi][1] = Ab[(r + 8) * STR + ko + q4];
                af[mi][2] = Ab[r * STR + ko + q4 + 4];
                af[mi][3] = Ab[(r + 8) * STR + ko + q4 + 4];
            }
            uint32_t bf_[8][2];
#pragma unroll
            for (int ni = 0; ni < 8; ni++) {
                int n = warp_n + ni * 8 + g;
                bf_[ni][0] = Bb[n * STR + ko + q4];
                bf_[ni][1] = Bb[n * STR + ko + q4 + 4];
            }
#pragma unroll
            for (int mi = 0; mi < 2; mi++)
#pragma unroll
                for (int ni = 0; ni < 8; ni++)
                    mma_bf16(acc[mi][ni], af[mi], bf_[ni]);
        }
        __syncthreads();
    }

    // epilogue: bias (+gelu) (+residual); out fp32 or bf16
#pragma unroll
    for (int mi = 0; mi < 2; mi++) {
        int ra = row0 + warp_m + mi * 16 + g;
        int rb = ra + 8;
#pragma unroll
        for (int ni = 0; ni < 8; ni++) {
            int col = col0 + warp_n + ni * 8 + q4 * 2;
            float b0 = bias[col], b1 = bias[col + 1];
            float v00 = acc[mi][ni][0] + b0, v01 = acc[mi][ni][1] + b1;
            float v10 = acc[mi][ni][2] + b0, v11 = acc[mi][ni][3] + b1;
            if (ACT == 1) {
                v00 = 0.5f * v00 * (1.0f + erff(v00 * 0.70710678118654752f));
                v01 = 0.5f * v01 * (1.0f + erff(v01 * 0.70710678118654752f));
                v10 = 0.5f * v10 * (1.0f + erff(v10 * 0.70710678118654752f));
                v11 = 0.5f * v11 * (1.0f + erff(v11 * 0.70710678118654752f));
            }
            if (HASRES) {
                float2 r0 = *(const float2*)(res + (size_t)ra * N + col);
                float2 r1 = *(const float2*)(res + (size_t)rb * N + col);
                v00 += r0.x; v01 += r0.y; v10 += r1.x; v11 += r1.y;
            }
            if (OUTBF) {
                bf16* C = (bf16*)Cout;
                __nv_bfloat162 p0 = __floats2bfloat162_rn(v00, v01);
                __nv_bfloat162 p1 = __floats2bfloat162_rn(v10, v11);
                *reinterpret_cast<uint32_t*>(C + (size_t)ra * N + col) = *reinterpret_cast<uint32_t*>(&p0);
                *reinterpret_cast<uint32_t*>(C + (size_t)rb * N + col) = *reinterpret_cast<uint32_t*>(&p1);
            } else {
                float* C = (float*)Cout;
                *(float2*)(C + (size_t)ra * N + col) = make_float2(v00, v01);
                *(float2*)(C + (size_t)rb * N + col) = make_float2(v10, v11);
            }
        }
    }
}

// ---------------- LayerNorm: warp per row, bf16 out -------------------------
__global__ void ln_kernel(const float* __restrict__ x,
                          const float* __restrict__ g,
                          const float* __restrict__ b,
                          bf16* __restrict__ y)
{
    const int row  = blockIdx.x * 8 + (threadIdx.x >> 5);
    const int lane = threadIdx.x & 31;
    const float4* xp = (const float4*)(x + (size_t)row * DMODEL);
    float4 u = xp[lane * 2], w = xp[lane * 2 + 1];

    float s = u.x + u.y + u.z + u.w + w.x + w.y + w.z + w.w;
#pragma unroll
    for (int off = 16; off; off >>= 1) s += __shfl_xor_sync(0xffffffffu, s, off);
    float mu = s * (1.f / DMODEL);

    float d0 = u.x - mu, d1 = u.y - mu, d2 = u.z - mu, d3 = u.w - mu;
    float d4 = w.x - mu, d5 = w.y - mu, d6 = w.z - mu, d7 = w.w - mu;
    float s2 = d0*d0 + d1*d1 + d2*d2 + d3*d3 + d4*d4 + d5*d5 + d6*d6 + d7*d7;
#pragma unroll
    for (int off = 16; off; off >>= 1) s2 += __shfl_xor_sync(0xffffffffu, s2, off);
    float inv = rsqrtf(s2 * (1.f / DMODEL) + LNEPS);

    const float4* gp = (const float4*)g;
    const float4* bp = (const float4*)b;
    float4 g0 = gp[lane * 2], g1 = gp[lane * 2 + 1];
    float4 b0 = bp[lane * 2], b1 = bp[lane * 2 + 1];

    __nv_bfloat162 p0 = __floats2bfloat162_rn(d0 * inv * g0.x + b0.x, d1 * inv * g0.y + b0.y);
    __nv_bfloat162 p1 = __floats2bfloat162_rn(d2 * inv * g0.z + b0.z, d3 * inv * g0.w + b0.w);
    __nv_bfloat162 p2 = __floats2bfloat162_rn(d4 * inv * g1.x + b1.x, d5 * inv * g1.y + b1.y);
    __nv_bfloat162 p3 = __floats2bfloat162_rn(d6 * inv * g1.z + b1.z, d7 * inv * g1.w + b1.w);
    uint4 o;
    o.x = *reinterpret_cast<uint32_t*>(&p0);
    o.y = *reinterpret_cast<uint32_t*>(&p1);
    o.z = *reinterpret_cast<uint32_t*>(&p2);
    o.w = *reinterpret_cast<uint32_t*>(&p3);
    *reinterpret_cast<uint4*>(y + (size_t)row * DMODEL + lane * 8) = o;
}

// ---------------- fused per-head QKV projection (bf16 io) -------------------
__global__ void qkv_kernel(const bf16* __restrict__ x1,
                           const float* __restrict__ wq, const float* __restrict__ bq,
                           const float* __restrict__ wk, const float* __restrict__ bk,
                           const float* __restrict__ wv, const float* __restrict__ bv,
                           bf16* __restrict__ q, bf16* __restrict__ k, bf16* __restrict__ v)
{
    __shared__ float wqs[32 * 33], wks[32 * 33], wvs[32 * 33];
    __shared__ float bqs[32], bks[32], bvs[32];
    __shared__ float xr[8][32];
    const int nh = blockIdx.x;
    const int n = nh / NHEAD, h = nh % NHEAD;
    const int t = threadIdx.x;
    const float* wqg = wq + (size_t)h * DH * DH;
    const float* wkg = wk + (size_t)h * DH * DH;
    const float* wvg = wv + (size_t)h * DH * DH;

    for (int i = t; i < DH * DH; i += 256) {
        int e = i >> 5, d = i & 31;
        wqs[e * 33 + d] = wqg[i];
        wks[e * 33 + d] = wkg[i];
        wvs[e * 33 + d] = wvg[i];
    }
    if (t < 32) { bqs[t] = bq[h * DH + t]; bks[t] = bk[h * DH + t]; bvs[t] = bv[h * DH + t]; }

    const int sl = t >> 5, lane = t & 31;
    const int s = blockIdx.y * 8 + sl;
    if (s < SEQ) xr[sl][lane] = __bfloat162float(x1[((size_t)n * SEQ + s) * DMODEL + h * DH + lane]);
    __syncthreads();
    if (s >= SEQ) return;

    float aq = bqs[lane], ak = bks[lane], av = bvs[lane];
#pragma unroll
    for (int d = 0; d < 32; d++) {
        float xv = xr[sl][d];
        aq += xv * wqs[lane * 33 + d];
        ak += xv * wks[lane * 33 + d];
        av += xv * wvs[lane * 33 + d];
    }
    size_t oidx = ((size_t)nh * SEQ + s) * DH + lane;
    q[oidx] = __float2bfloat16(aq);
    k[oidx] = __float2bfloat16(ak);
    v[oidx] = __float2bfloat16(av);
}

// ---------------- tensor-core flash attention per (n,h) ---------------------
// 7 warps x 32 query rows, K tiles of 32, online softmax in mma fragments.
#define SPAD 224
#define NKT  7
#define KSTR 20      // u32 per K row (16 data + 4 pad)
#define VSTR 116     // u32 per VT row (112 data + 4 pad)

__global__ void __launch_bounds__(224) attn_tc(const bf16* __restrict__ q,
                                               const bf16* __restrict__ k,
                                               const bf16* __restrict__ v,
                                               bf16* __restrict__ o)
{
    __shared__ uint32_t Ks[SPAD * KSTR];
    __shared__ uint32_t VT[32 * VSTR];

    const int nh = blockIdx.x;
    const int n = nh / NHEAD, h = nh % NHEAD;
    const int t = threadIdx.x, warp = t >> 5, lane = t & 31;
    const int g = lane >> 2, q4 = lane & 3;
    const size_t base = (size_t)nh * SEQ * DH;
    const uint32_t* q32 = (const uint32_t*)(q + base);
    const uint32_t* k32 = (const uint32_t*)(k + base);

    // stage K (zero-pad rows >= SEQ)
    for (int i = t; i < SPAD * 16; i += 224) {
        int r = i >> 4, c = i & 15;
        Ks[r * KSTR + c] = (r < SEQ) ? k32[r * 16 + c] : 0u;
    }
    // stage V transposed: VT16[e][t]
    bf16* VT16 = (bf16*)VT;
    for (int i = t; i < SPAD * 32; i += 224) {
        int tt = i >> 5, e = i & 31;
        VT16[e * (VSTR * 2) + tt] = (tt < SEQ) ? v[base + tt * 32 + e] : __float2bfloat16(0.f);
    }
    __syncthreads();

    // Q fragments, direct from gmem (zero for rows >= SEQ)
    const int qbase = warp * 32;
    uint32_t qf[2][2][4];
#pragma unroll
    for (int mi = 0; mi < 2; mi++) {
        int r0 = qbase + mi * 16 + g, r1 = r0 + 8;
        bool v0 = r0 < SEQ, v1 = r1 < SEQ;
#pragma unroll
        for (int ks = 0; ks < 2; ks++) {
            qf[mi][ks][0] = v0 ? q32[r0 * 16 + ks * 8 + q4]     : 0u;
            qf[mi][ks][1] = v1 ? q32[r1 * 16 + ks * 8 + q4]     : 0u;
            qf[mi][ks][2] = v0 ? q32[r0 * 16 + ks * 8 + q4 + 4] : 0u;
            qf[mi][ks][3] = v1 ? q32[r1 * 16 + ks * 8 + q4 + 4] : 0u;
        }
    }

    float Oa[2][4][4];
#pragma unroll
    for (int mi = 0; mi < 2; mi++)
#pragma unroll
        for (int ne = 0; ne < 4; ne++)
#pragma unroll
            for (int e = 0; e < 4; e++) Oa[mi][ne][e] = 0.f;
    float m_[2][2] = {{-1e30f, -1e30f}, {-1e30f, -1e30f}};
    float l_[2][2] = {{0.f, 0.f}, {0.f, 0.f}};
    const float scale = 0.17677669529663689f;

    for (int kt = 0; kt < NKT; kt++) {
        // scores
        float sc[2][4][4];
#pragma unroll
        for (int mi = 0; mi < 2; mi++)
#pragma unroll
            for (int ni = 0; ni < 4; ni++)
#pragma unroll
                for (int e = 0; e < 4; e++) sc[mi][ni][e] = 0.f;

        uint32_t kf[2][4][2];
#pragma unroll
        for (int ks = 0; ks < 2; ks++)
#pragma unroll
            for (int ni = 0; ni < 4; ni++) {
                int r = kt * 32 + ni * 8 + g;
                kf[ks][ni][0] = Ks[r * KSTR + ks * 8 + q4];
                kf[ks][ni][1] = Ks[r * KSTR + ks * 8 + q4 + 4];
            }
#pragma unroll
        for (int mi = 0; mi < 2; mi++)
#pragma unroll
            for (int ni = 0; ni < 4; ni++)
#pragma unroll
                for (int ks = 0; ks < 2; ks++)
                    mma_bf16(sc[mi][ni], qf[mi][ks], kf[ks][ni]);

        // softmax (online), per row-half
#pragma unroll
        for (int mi = 0; mi < 2; mi++) {
#pragma unroll
            for (int hf = 0; hf < 2; hf++) {
                float mx = -1e30f;
#pragma unroll
                for (int ni = 0; ni < 4; ni++) {
                    int col = kt * 32 + ni * 8 + q4 * 2;
                    float s0 = (col     < SEQ) ? sc[mi][ni][hf * 2]     * scale : -1e30f;
                    float s1 = (col + 1 < SEQ) ? sc[mi][ni][hf * 2 + 1] * scale : -1e30f;
                    sc[mi][ni][hf * 2]     = s0;
                    sc[mi][ni][hf * 2 + 1] = s1;
                    mx = fmaxf(mx, fmaxf(s0, s1));
                }
                mx = fmaxf(mx, __shfl_xor_sync(0xffffffffu, mx, 1));
                mx = fmaxf(mx, __shfl_xor_sync(0xffffffffu, mx, 2));
                float mnew = fmaxf(m_[mi][hf], mx);
                float f = __expf(m_[mi][hf] - mnew);
                m_[mi][hf] = mnew;
                float rs = 0.f;
#pragma unroll
                for (int ni = 0; ni < 4; ni++) {
                    float p0 = __expf(sc[mi][ni][hf * 2]     - mnew);
                    float p1 = __expf(sc[mi][ni][hf * 2 + 1] - mnew);
                    sc[mi][ni][hf * 2]     = p0;
                    sc[mi][ni][hf * 2 + 1] = p1;
                    rs += p0 + p1;
                }
                rs += __shfl_xor_sync(0xffffffffu, rs, 1);
                rs += __shfl_xor_sync(0xffffffffu, rs, 2);
                l_[mi][hf] = l_[mi][hf] * f + rs;
#pragma unroll
                for (int ne = 0; ne < 4; ne++) {
                    Oa[mi][ne][hf * 2]     *= f;
                    Oa[mi][ne][hf * 2 + 1] *= f;
                }
            }
        }

        // pack P into A fragments
        uint32_t pa[2][2][4];
#pragma unroll
        for (int mi = 0; mi < 2; mi++)
#pragma unroll
            for (int ks = 0; ks < 2; ks++) {
                __nv_bfloat162 t0 = __floats2bfloat162_rn(sc[mi][2 * ks][0],     sc[mi][2 * ks][1]);
                __nv_bfloat162 t1 = __floats2bfloat162_rn(sc[mi][2 * ks][2],     sc[mi][2 * ks][3]);
                __nv_bfloat162 t2 = __floats2bfloat162_rn(sc[mi][2 * ks + 1][0], sc[mi][2 * ks + 1][1]);
                __nv_bfloat162 t3 = __floats2bfloat162_rn(sc[mi][2 * ks + 1][2], sc[mi][2 * ks + 1][3]);
                pa[mi][ks][0] = *reinterpret_cast<uint32_t*>(&t0);
                pa[mi][ks][1] = *reinterpret_cast<uint32_t*>(&t1);
                pa[mi][ks][2] = *reinterpret_cast<uint32_t*>(&t2);
                pa[mi][ks][3] = *reinterpret_cast<uint32_t*>(&t3);
            }

        // PV
        uint32_t vf[2][4][2];
#pragma unroll
        for (int ks = 0; ks < 2; ks++)
#pragma unroll
            for (int ne = 0; ne < 4; ne++) {
                int r = ne * 8 + g;
                int cu = kt * 16 + ks * 8 + q4;
                vf[ks][ne][0] = VT[r * VSTR + cu];
                vf[ks][ne][1] = VT[r * VSTR + cu + 4];
            }
#pragma unroll
        for (int mi = 0; mi < 2; mi++)
#pragma unroll
            for (int ne = 0; ne < 4; ne++)
#pragma unroll
                for (int ks = 0; ks < 2; ks++)
                    mma_bf16(Oa[mi][ne], pa[mi][ks], vf[ks][ne]);
    }

    // write output: o[n][s][h*32 + e]
#pragma unroll
    for (int mi = 0; mi < 2; mi++) {
#pragma unroll
        for (int hf = 0; hf < 2; hf++) {
            int row = qbase + mi * 16 + hf * 8 + g;
            if (row >= SEQ) continue;
            float inv = 1.f / l_[mi][hf];
            bf16* op = o + ((size_t)n * SEQ + row) * DMODEL + h * DH;
#pragma unroll
            for (int ne = 0; ne < 4; ne++) {
                __nv_bfloat162 p = __floats2bfloat162_rn(Oa[mi][ne][hf * 2] * inv,
                                                         Oa[mi][ne][hf * 2 + 1] * inv);
                *reinterpret_cast<uint32_t*>(op + ne * 8 + q4 * 2) = *reinterpret_cast<uint32_t*>(&p);
            }
        }
    }
}

// ---------------- classification head ---------------------------------------
__global__ void head_kernel(const float* __restrict__ X, const float* __restrict__ w_out,
                            const float* __restrict__ b_out, float* __restrict__ out)
{
    __shared__ float cls_s[DMODEL];
    __shared__ float logits[OUTC];
    __shared__ float red[8];
    const int n = blockIdx.x;
    const int t = threadIdx.x, wid = t >> 5, lane = t & 31;

    cls_s[t] = X[(size_t)n * SEQ * DMODEL + t];
    __syncthreads();

    for (int j = wid; j < OUTC; j += 8) {
        float acc = 0.f;
#pragma unroll
        for (int k = lane; k < DMODEL; k += 32) acc += cls_s[k] * w_out[(size_t)j * DMODEL + k];
#pragma unroll
        for (int off = 16; off; off >>= 1) acc += __shfl_xor_sync(0xffffffffu, acc, off);
        if (lane == 0) logits[j] = acc + b_out[j];
    }
    __syncthreads();

    float mx = -1e30f;
    for (int j = t; j < OUTC; j += 256) mx = fmaxf(mx, logits[j]);
#pragma unroll
    for (int off = 16; off; off >>= 1) mx = fmaxf(mx, __shfl_xor_sync(0xffffffffu, mx, off));
    if (lane == 0) red[wid] = mx;
    __syncthreads();
    float bm = -1e30f;
#pragma unroll
    for (int i = 0; i < 8; i++) bm = fmaxf(bm, red[i]);
    __syncthreads();

    float sum = 0.f;
    for (int j = t; j < OUTC; j += 256) {
        float e = __expf(logits[j] - bm);
        logits[j] = e;
        sum += e;
    }
#pragma unroll
    for (int off = 16; off; off >>= 1) sum += __shfl_xor_sync(0xffffffffu, sum, off);
    if (lane == 0) red[wid] = sum;
    __syncthreads();
    float bs = 0.f;
#pragma unroll
    for (int i = 0; i < 8; i++) bs += red[i];
    float inv = 1.f / bs;
    __syncthreads();
    for (int j = t; j < OUTC; j += 256) out[(size_t)n * OUTC + j] = logits[j] * inv;
}

// ---------------- launcher ----------------
extern "C" void kernel_launch(void* const* d_in, const int* in_sizes, int n_in,
                              void* d_out, int out_size)
{
    const float* images  = (const float*)d_in[0];
    const float* w_map   = (const float*)d_in[1];
    const float* b_map   = (const float*)d_in[2];
    const float* cls_tok = (const float*)d_in[3];
    const float* norm1_g = (const float*)d_in[4];
    const float* norm1_b = (const float*)d_in[5];
    const float* wq      = (const float*)d_in[6];
    const float* bq      = (const float*)d_in[7];
    const float* wk      = (const float*)d_in[8];
    const float* bk      = (const float*)d_in[9];
    const float* wv      = (const float*)d_in[10];
    const float* bv      = (const float*)d_in[11];
    const float* w_last  = (const float*)d_in[12];
    const float* b_last  = (const float*)d_in[13];
    const float* norm2_g = (const float*)d_in[14];
    const float* norm2_b = (const float*)d_in[15];
    const float* w_mlp1  = (const float*)d_in[16];
    const float* b_mlp1  = (const float*)d_in[17];
    const float* w_mlp2  = (const float*)d_in[18];
    const float* b_mlp2  = (const float*)d_in[19];
    const float* w_out   = (const float*)d_in[20];
    const float* b_out   = (const float*)d_in[21];
    float* out = (float*)d_out;

    bf16 *patches, *x1b, *qb, *kb, *vb, *ob, *h1b, *wmapb, *wlastb, *wmlp1b, *wmlp2b;
    float *X, *tok, *pe;
    cudaGetSymbolAddress((void**)&patches, g_patches_b);
    cudaGetSymbolAddress((void**)&tok, g_tok);
    cudaGetSymbolAddress((void**)&X,   g_X);
    cudaGetSymbolAddress((void**)&x1b, g_x1b);
    cudaGetSymbolAddress((void**)&qb,  g_qb);
    cudaGetSymbolAddress((void**)&kb,  g_kb);
    cudaGetSymbolAddress((void**)&vb,  g_vb);
    cudaGetSymbolAddress((void**)&ob,  g_ob);
    cudaGetSymbolAddress((void**)&h1b, g_h1b);
    cudaGetSymbolAddress((void**)&pe,  g_pe);
    cudaGetSymbolAddress((void**)&wmapb,  g_wmapb);
    cudaGetSymbolAddress((void**)&wlastb, g_wlastb);
    cudaGetSymbolAddress((void**)&wmlp1b, g_wmlp1b);
    cudaGetSymbolAddress((void**)&wmlp2b, g_wmlp2b);

    cudaFuncSetAttribute(gemm_bf<0, false, false>, cudaFuncAttributeMaxDynamicSharedMemorySize, GEMM_SMEM);
    cudaFuncSetAttribute(gemm_bf<0, true,  false>, cudaFuncAttributeMaxDynamicSharedMemorySize, GEMM_SMEM);
    cudaFuncSetAttribute(gemm_bf<1, false, true >, cudaFuncAttributeMaxDynamicSharedMemorySize, GEMM_SMEM);

    // 0) weight conversion to bf16
    {
        int n1 = DMODEL * IN_D;
        cvt_kernel<<<(n1 / 4 + 255) / 256, 256>>>(w_map, wmapb, n1);
        int n2 = NLAYER * DMODEL * DMODEL;
        cvt_kernel<<<(n2 / 4 + 255) / 256, 256>>>(w_last, wlastb, n2);
        int n3 = NLAYER * 4 * DMODEL * DMODEL;
        cvt_kernel<<<(n3 / 4 + 255) / 256, 256>>>(w_mlp1, wmlp1b, n3);
        cvt_kernel<<<(n3 / 4 + 255) / 256, 256>>>(w_mlp2, wmlp2b, n3);
    }

    // 1) patches + PE table
    {
        int tot = BATCH * NP * IN_D;
        patch_kernel<<<(tot + 255) / 256, 256>>>(images, patches);
        int pt = SEQ * DMODEL;
        pe_kernel<<<(pt + 255) / 256, 256>>>(pe);
    }

    // 2) patch-embed GEMM: tok = patches @ w_map^T + b_map  (25088, 256, 768)
    gemm_bf<0, false, false><<<dim3(DMODEL / 128, (BATCH * NP) / 128), 256, GEMM_SMEM>>>(
        patches, wmapb, b_map, nullptr, tok, BATCH * NP, DMODEL, IN_D);

    // 3) X = concat(cls, tok) + pe
    {
        int tot = BATCH * SEQ * DMODEL;
        assemble_kernel<<<(tot + 255) / 256, 256>>>(tok, cls_tok, pe, X);
    }

    const int MROWS = BATCH * SEQ;   // 25216 = 128*197

    for (int l = 0; l < NLAYER; l++) {
        ln_kernel<<<MROWS / 8, 256>>>(X, norm1_g + l * DMODEL, norm1_b + l * DMODEL, x1b);

        qkv_kernel<<<dim3(BATCH * NHEAD, (SEQ + 7) / 8), 256>>>(
            x1b,
            wq + (size_t)l * NHEAD * DH * DH, bq + (size_t)l * NHEAD * DH,
            wk + (size_t)l * NHEAD * DH * DH, bk + (size_t)l * NHEAD * DH,
            wv + (size_t)l * NHEAD * DH * DH, bv + (size_t)l * NHEAD * DH,
            qb, kb, vb);

        attn_tc<<<BATCH * NHEAD, 224>>>(qb, kb, vb, ob);

        // o-proj + residual: X = X + o @ w_last^T + b_last (25216,256,256)
        gemm_bf<0, true, false><<<dim3(DMODEL / 128, MROWS / 128), 256, GEMM_SMEM>>>(
            ob, wlastb + (size_t)l * DMODEL * DMODEL, b_last + l * DMODEL, X, X,
            MROWS, DMODEL, DMODEL);

        ln_kernel<<<MROWS / 8, 256>>>(X, norm2_g + l * DMODEL, norm2_b + l * DMODEL, x1b);

        // MLP1 + GELU -> bf16 h1 (25216,1024,256)
        gemm_bf<1, false, true><<<dim3((4 * DMODEL) / 128, MROWS / 128), 256, GEMM_SMEM>>>(
            x1b, wmlp1b + (size_t)l * 4 * DMODEL * DMODEL, b_mlp1 + l * 4 * DMODEL,
            nullptr, h1b, MROWS, 4 * DMODEL, DMODEL);

        // MLP2 + residual: X = X + h1 @ w_mlp2^T + b2 (25216,256,1024)
        gemm_bf<0, true, false><<<dim3(DMODEL / 128, MROWS / 128), 256, GEMM_SMEM>>>(
            h1b, wmlp2b + (size_t)l * 4 * DMODEL * DMODEL, b_mlp2 + l * DMODEL, X, X,
            MROWS, DMODEL, 4 * DMODEL);
    }

    head_kernel<<<BATCH, 256>>>(X, w_out, b_out, out);
}

// round 6
// speedup vs baseline: 4.6193x; 1.0771x over previous
#include <cuda_runtime.h>
#include <cuda_bf16.h>
#include <math.h>
#include <stdint.h>

// ---------------- problem constants ----------------
#define BATCH 128
#define CH    3
#define HIM   224
#define PGRID 14
#define NP    196
#define PATCH 16
#define IN_D  768
#define DMODEL 256
#define NHEAD 8
#define DH    32
#define NLAYER 4
#define SEQ   197
#define OUTC  1000
#define LNEPS 1e-5f

typedef __nv_bfloat16 bf16;

// ---------------- scratch (device globals) ----------------
__device__ bf16  g_patches_b[BATCH * NP * IN_D];
__device__ float g_X [BATCH * SEQ * DMODEL];
__device__ bf16  g_x1b[BATCH * SEQ * DMODEL];
__device__ bf16  g_qb [BATCH * SEQ * DMODEL];             // [n,h,s,e]
__device__ bf16  g_kb [BATCH * SEQ * DMODEL];
__device__ bf16  g_vb [BATCH * SEQ * DMODEL];
__device__ bf16  g_ob [BATCH * SEQ * DMODEL];             // [n,s,d]
__device__ bf16  g_h1b[BATCH * SEQ * 4 * DMODEL];
__device__ float g_pe[SEQ * DMODEL];
__device__ bf16  g_wmapb [DMODEL * IN_D];
__device__ bf16  g_wlastb[NLAYER * DMODEL * DMODEL];
__device__ bf16  g_wmlp1b[NLAYER * 4 * DMODEL * DMODEL];
__device__ bf16  g_wmlp2b[NLAYER * 4 * DMODEL * DMODEL];

// ---------------- fp32 -> bf16 convert ----------------
__global__ void cvt_kernel(const float* __restrict__ src, bf16* __restrict__ dst, int n)
{
    int i = (blockIdx.x * 256 + threadIdx.x) * 4;
    if (i >= n) return;
    float4 v = *(const float4*)(src + i);
    __nv_bfloat162 p0 = __floats2bfloat162_rn(v.x, v.y);
    __nv_bfloat162 p1 = __floats2bfloat162_rn(v.z, v.w);
    uint2 o;
    o.x = *reinterpret_cast<uint32_t*>(&p0);
    o.y = *reinterpret_cast<uint32_t*>(&p1);
    *reinterpret_cast<uint2*>(dst + i) = o;
}

// ---------------- patch extraction (writes bf16) ----------------
__global__ void patch_kernel(const float* __restrict__ img, bf16* __restrict__ out)
{
    int idx = blockIdx.x * 256 + threadIdx.x;
    if (idx >= BATCH * NP * IN_D) return;
    int i = idx % IN_D;
    int p = (idx / IN_D) % NP;
    int n = idx / (IN_D * NP);
    int c   = i >> 8;
    int r   = (i >> 4) & 15;
    int col = i & 15;
    int py = p / PGRID, px = p % PGRID;
    out[idx] = __float2bfloat16(
        img[(((size_t)n * CH + c) * HIM + py * PATCH + r) * HIM + px * PATCH + col]);
}

// ---------------- positional encoding (fp64) ----------------
__global__ void pe_kernel(float* __restrict__ pe)
{
    int i = blockIdx.x * 256 + threadIdx.x;
    if (i >= SEQ * DMODEL) return;
    int s = i / DMODEL, d = i % DMODEL;
    double expo = (double)(2 * (d / 2)) / (double)DMODEL;
    double ang  = (double)s / pow(10000.0, expo);
    pe[i] = (float)((d & 1) ? cos(ang) : sin(ang));
}

// ---------------- cls rows: X[n][0][:] = cls + pe[0] ------------------------
__global__ void cls_kernel(const float* __restrict__ cls,
                           const float* __restrict__ pe,
                           float* __restrict__ X)
{
    int i = blockIdx.x * 256 + threadIdx.x;
    if (i >= BATCH * DMODEL) return;
    int d = i % DMODEL;
    int n = i / DMODEL;
    X[(size_t)n * SEQ * DMODEL + d] = cls[d] + pe[d];
}

// ---------------- bf16 MMA / ldmatrix helpers -------------------------------
__device__ __forceinline__ void mma_bf16(float* c, const uint32_t* a, const uint32_t* b)
{
    asm volatile(
        "mma.sync.aligned.m16n8k16.row.col.f32.bf16.bf16.f32 "
        "{%0,%1,%2,%3}, {%4,%5,%6,%7}, {%8,%9}, {%0,%1,%2,%3};"
        : "+f"(c[0]), "+f"(c[1]), "+f"(c[2]), "+f"(c[3])
        : "r"(a[0]), "r"(a[1]), "r"(a[2]), "r"(a[3]), "r"(b[0]), "r"(b[1]));
}

#define LDSM4(r0, r1, r2, r3, addr) \
    asm volatile("ldmatrix.sync.aligned.m8n8.x4.shared.b16 {%0,%1,%2,%3}, [%4];" \
                 : "=r"(r0), "=r"(r1), "=r"(r2), "=r"(r3) : "r"(addr))

#define CP16(dst, src) asm volatile("cp.async.cg.shared.global [%0], [%1], 16;\n" :: "r"(dst), "l"(src))
#define CP_COMMIT()    asm volatile("cp.async.commit_group;\n" ::)
#define CP_WAIT1()     asm volatile("cp.async.wait_group 1;\n" ::)
#define CP_WAIT0()     asm volatile("cp.async.wait_group 0;\n" ::)

// ---------------- bf16 tensor-core GEMM, 128x128 tile, ldmatrix -------------
// C = act(A @ W^T + bias) (+res) (+pe-remap for patch embed).
// A:[M,K] bf16, W:[N,K] bf16, row-major. K-tile 64, 8 warps (4m x 2n).
// Requires M%128==0, N%128==0, K%64==0.
#define STR 36                      // u32 stride per 64-bf16 row (pad 4) = 144B
#define ABUF (128 * STR)            // u32
#define GEMM_SMEM (4 * ABUF * 4)    // A0,A1,B0,B1

template<int ACT, bool HASRES, bool OUTBF, bool ADDPE>
__global__ void __launch_bounds__(256) gemm_bf(const bf16* __restrict__ A,
                                               const bf16* __restrict__ W,
                                               const float* __restrict__ bias,
                                               const float* __restrict__ res,
                                               const float* __restrict__ pe,
                                               void* __restrict__ Cout,
                                               int M, int N, int K)
{
    extern __shared__ uint32_t sm_[];
    const uint32_t smem_byte = (uint32_t)__cvta_generic_to_shared(sm_);

    const int t    = threadIdx.x;
    const int warp = t >> 5, lane = t & 31;
    const int g    = lane >> 2, q4 = lane & 3;
    const int warp_m = (warp >> 1) * 32;
    const int warp_n = (warp & 1) * 64;
    const int row0 = blockIdx.y * 128, col0 = blockIdx.x * 128;

    float acc[2][8][4];
#pragma unroll
    for (int mi = 0; mi < 2; mi++)
#pragma unroll
        for (int ni = 0; ni < 8; ni++)
#pragma unroll
            for (int e = 0; e < 4; e++) acc[mi][ni][e] = 0.f;

    auto stage = [&](int k0, int buf) {
        uint32_t abase = smem_byte + buf * (ABUF * 4);
        uint32_t bbase = smem_byte + (2 + buf) * (ABUF * 4);
#pragma unroll
        for (int i = 0; i < 4; i++) {
            int c = t + i * 256;
            int r = c >> 3, co = c & 7;
            CP16(abase + (r * STR + co * 4) * 4, A + (size_t)(row0 + r) * K + k0 + co * 8);
            CP16(bbase + (r * STR + co * 4) * 4, W + (size_t)(col0 + r) * K + k0 + co * 8);
        }
        CP_COMMIT();
    };

    // ldmatrix source addresses (per thread), for each buffer
    // A (x4): lanes 0-15 -> rows (warp_m + mi*16 + lane&15), byte k0;
    //         lanes 16-31 -> same rows, byte k0+16
    // B (x4): covers n-tiles 2nj,2nj+1: lane quads -> rows/k-halves
    uint32_t a_addr[2][2], b_addr[2][4];
    {
        int ar = warp_m + (lane & 15);
        int ab = (lane >> 4) * 16;
        int br = warp_n + ((lane >> 4) & 1) * 8 + (lane & 7);
        int bb = ((lane >> 3) & 1) * 16;
#pragma unroll
        for (int buf = 0; buf < 2; buf++) {
            uint32_t abase = smem_byte + buf * (ABUF * 4);
            uint32_t bbase = smem_byte + (2 + buf) * (ABUF * 4);
#pragma unroll
            for (int mi = 0; mi < 2; mi++)
                a_addr[buf][mi] = abase + (ar + mi * 16) * (STR * 4) + ab;
#pragma unroll
            for (int nj = 0; nj < 4; nj++)
                b_addr[buf][nj] = bbase + (br + nj * 16) * (STR * 4) + bb;
        }
    }

    const int KT = K >> 6;
    stage(0, 0);

    for (int kt = 0; kt < KT; kt++) {
        const int cur = kt & 1;
        if (kt + 1 < KT) { stage((kt + 1) << 6, cur ^ 1); CP_WAIT1(); }
        else             { CP_WAIT0(); }
        __syncthreads();

#pragma unroll
        for (int ks = 0; ks < 4; ks++) {
            const uint32_t kb = ks * 32;
            uint32_t af[2][4];
            LDSM4(af[0][0], af[0][1], af[0][2], af[0][3], a_addr[cur][0] + kb);
            LDSM4(af[1][0], af[1][1], af[1][2], af[1][3], a_addr[cur][1] + kb);
            uint32_t bf_[8][2];
#pragma unroll
            for (int nj = 0; nj < 4; nj++)
                LDSM4(bf_[2 * nj][0], bf_[2 * nj][1], bf_[2 * nj + 1][0], bf_[2 * nj + 1][1],
                      b_addr[cur][nj] + kb);
#pragma unroll
            for (int mi = 0; mi < 2; mi++)
#pragma unroll
                for (int ni = 0; ni < 8; ni++)
                    mma_bf16(acc[mi][ni], af[mi], bf_[ni]);
        }
        __syncthreads();
    }

    // epilogue: bias (+gelu) (+residual) (+pe remap); out fp32 or bf16
#pragma unroll
    for (int mi = 0; mi < 2; mi++) {
        int ra = row0 + warp_m + mi * 16 + g;
        int rb = ra + 8;
        size_t orow_a, orow_b;
        if (ADDPE) {
            orow_a = (size_t)(ra / NP) * SEQ + (ra % NP) + 1;
            orow_b = (size_t)(rb / NP) * SEQ + (rb % NP) + 1;
        } else {
            orow_a = ra; orow_b = rb;
        }
        int pes_a = ADDPE ? ((ra % NP) + 1) : 0;
        int pes_b = ADDPE ? ((rb % NP) + 1) : 0;
#pragma unroll
        for (int ni = 0; ni < 8; ni++) {
            int col = col0 + warp_n + ni * 8 + q4 * 2;
            float b0 = bias[col], b1 = bias[col + 1];
            float v00 = acc[mi][ni][0] + b0, v01 = acc[mi][ni][1] + b1;
            float v10 = acc[mi][ni][2] + b0, v11 = acc[mi][ni][3] + b1;
            if (ACT == 1) {
                v00 = 0.5f * v00 * (1.0f + erff(v00 * 0.70710678118654752f));
                v01 = 0.5f * v01 * (1.0f + erff(v01 * 0.70710678118654752f));
                v10 = 0.5f * v10 * (1.0f + erff(v10 * 0.70710678118654752f));
                v11 = 0.5f * v11 * (1.0f + erff(v11 * 0.70710678118654752f));
            }
            if (HASRES) {
                float2 r0 = *(const float2*)(res + orow_a * N + col);
                float2 r1 = *(const float2*)(res + orow_b * N + col);
                v00 += r0.x; v01 += r0.y; v10 += r1.x; v11 += r1.y;
            }
            if (ADDPE) {
                float2 p0 = *(const float2*)(pe + (size_t)pes_a * DMODEL + col);
                float2 p1 = *(const float2*)(pe + (size_t)pes_b * DMODEL + col);
                v00 += p0.x; v01 += p0.y; v10 += p1.x; v11 += p1.y;
            }
            if (OUTBF) {
                bf16* C = (bf16*)Cout;
                __nv_bfloat162 p0 = __floats2bfloat162_rn(v00, v01);
                __nv_bfloat162 p1 = __floats2bfloat162_rn(v10, v11);
                *reinterpret_cast<uint32_t*>(C + orow_a * N + col) = *reinterpret_cast<uint32_t*>(&p0);
                *reinterpret_cast<uint32_t*>(C + orow_b * N + col) = *reinterpret_cast<uint32_t*>(&p1);
            } else {
                float* C = (float*)Cout;
                *(float2*)(C + orow_a * N + col) = make_float2(v00, v01);
                *(float2*)(C + orow_b * N + col) = make_float2(v10, v11);
            }
        }
    }
}

// ---------------- LayerNorm: warp per row, bf16 out -------------------------
__global__ void ln_kernel(const float* __restrict__ x,
                          const float* __restrict__ g,
                          const float* __restrict__ b,
                          bf16* __restrict__ y)
{
    const int row  = blockIdx.x * 8 + (threadIdx.x >> 5);
    const int lane = threadIdx.x & 31;
    const float4* xp = (const float4*)(x + (size_t)row * DMODEL);
    float4 u = xp[lane * 2], w = xp[lane * 2 + 1];

    float s = u.x + u.y + u.z + u.w + w.x + w.y + w.z + w.w;
#pragma unroll
    for (int off = 16; off; off >>= 1) s += __shfl_xor_sync(0xffffffffu, s, off);
    float mu = s * (1.f / DMODEL);

    float d0 = u.x - mu, d1 = u.y - mu, d2 = u.z - mu, d3 = u.w - mu;
    float d4 = w.x - mu, d5 = w.y - mu, d6 = w.z - mu, d7 = w.w - mu;
    float s2 = d0*d0 + d1*d1 + d2*d2 + d3*d3 + d4*d4 + d5*d5 + d6*d6 + d7*d7;
#pragma unroll
    for (int off = 16; off; off >>= 1) s2 += __shfl_xor_sync(0xffffffffu, s2, off);
    float inv = rsqrtf(s2 * (1.f / DMODEL) + LNEPS);

    const float4* gp = (const float4*)g;
    const float4* bp = (const float4*)b;
    float4 g0 = gp[lane * 2], g1 = gp[lane * 2 + 1];
    float4 b0 = bp[lane * 2], b1 = bp[lane * 2 + 1];

    __nv_bfloat162 p0 = __floats2bfloat162_rn(d0 * inv * g0.x + b0.x, d1 * inv * g0.y + b0.y);
    __nv_bfloat162 p1 = __floats2bfloat162_rn(d2 * inv * g0.z + b0.z, d3 * inv * g0.w + b0.w);
    __nv_bfloat162 p2 = __floats2bfloat162_rn(d4 * inv * g1.x + b1.x, d5 * inv * g1.y + b1.y);
    __nv_bfloat162 p3 = __floats2bfloat162_rn(d6 * inv * g1.z + b1.z, d7 * inv * g1.w + b1.w);
    uint4 o;
    o.x = *reinterpret_cast<uint32_t*>(&p0);
    o.y = *reinterpret_cast<uint32_t*>(&p1);
    o.z = *reinterpret_cast<uint32_t*>(&p2);
    o.w = *reinterpret_cast<uint32_t*>(&p3);
    *reinterpret_cast<uint4*>(y + (size_t)row * DMODEL + lane * 8) = o;
}

// ---------------- fused per-head QKV projection (bf16 io) -------------------
__global__ void qkv_kernel(const bf16* __restrict__ x1,
                           const float* __restrict__ wq, const float* __restrict__ bq,
                           const float* __restrict__ wk, const float* __restrict__ bk,
                           const float* __restrict__ wv, const float* __restrict__ bv,
                           bf16* __restrict__ q, bf16* __restrict__ k, bf16* __restrict__ v)
{
    __shared__ float wqs[32 * 33], wks[32 * 33], wvs[32 * 33];
    __shared__ float bqs[32], bks[32], bvs[32];
    __shared__ float xr[8][32];
    const int nh = blockIdx.x;
    const int n = nh / NHEAD, h = nh % NHEAD;
    const int t = threadIdx.x;
    const float* wqg = wq + (size_t)h * DH * DH;
    const float* wkg = wk + (size_t)h * DH * DH;
    const float* wvg = wv + (size_t)h * DH * DH;

    for (int i = t; i < DH * DH; i += 256) {
        int e = i >> 5, d = i & 31;
        wqs[e * 33 + d] = wqg[i];
        wks[e * 33 + d] = wkg[i];
        wvs[e * 33 + d] = wvg[i];
    }
    if (t < 32) { bqs[t] = bq[h * DH + t]; bks[t] = bk[h * DH + t]; bvs[t] = bv[h * DH + t]; }

    const int sl = t >> 5, lane = t & 31;
    const int s = blockIdx.y * 8 + sl;
    if (s < SEQ) xr[sl][lane] = __bfloat162float(x1[((size_t)n * SEQ + s) * DMODEL + h * DH + lane]);
    __syncthreads();
    if (s >= SEQ) return;

    float aq = bqs[lane], ak = bks[lane], av = bvs[lane];
#pragma unroll
    for (int d = 0; d < 32; d++) {
        float xv = xr[sl][d];
        aq += xv * wqs[lane * 33 + d];
        ak += xv * wks[lane * 33 + d];
        av += xv * wvs[lane * 33 + d];
    }
    size_t oidx = ((size_t)nh * SEQ + s) * DH + lane;
    q[oidx] = __float2bfloat16(aq);
    k[oidx] = __float2bfloat16(ak);
    v[oidx] = __float2bfloat16(av);
}

// ---------------- tensor-core flash attention per (n,h) ---------------------
#define SPAD 224
#define NKT  7
#define KSTR 20
#define VSTR 116

__global__ void __launch_bounds__(224) attn_tc(const bf16* __restrict__ q,
                                               const bf16* __restrict__ k,
                                               const bf16* __restrict__ v,
                                               bf16* __restrict__ o)
{
    __shared__ uint32_t Ks[SPAD * KSTR];
    __shared__ uint32_t VT[32 * VSTR];

    const int nh = blockIdx.x;
    const int n = nh / NHEAD, h = nh % NHEAD;
    const int t = threadIdx.x, warp = t >> 5, lane = t & 31;
    const int g = lane >> 2, q4 = lane & 3;
    const size_t base = (size_t)nh * SEQ * DH;
    const uint32_t* q32 = (const uint32_t*)(q + base);
    const uint32_t* k32 = (const uint32_t*)(k + base);

    for (int i = t; i < SPAD * 16; i += 224) {
        int r = i >> 4, c = i & 15;
        Ks[r * KSTR + c] = (r < SEQ) ? k32[r * 16 + c] : 0u;
    }
    bf16* VT16 = (bf16*)VT;
    for (int i = t; i < SPAD * 32; i += 224) {
        int tt = i >> 5, e = i & 31;
        VT16[e * (VSTR * 2) + tt] = (tt < SEQ) ? v[base + tt * 32 + e] : __float2bfloat16(0.f);
    }
    __syncthreads();

    const int qbase = warp * 32;
    uint32_t qf[2][2][4];
#pragma unroll
    for (int mi = 0; mi < 2; mi++) {
        int r0 = qbase + mi * 16 + g, r1 = r0 + 8;
        bool v0 = r0 < SEQ, v1 = r1 < SEQ;
#pragma unroll
        for (int ks = 0; ks < 2; ks++) {
            qf[mi][ks][0] = v0 ? q32[r0 * 16 + ks * 8 + q4]     : 0u;
            qf[mi][ks][1] = v1 ? q32[r1 * 16 + ks * 8 + q4]     : 0u;
            qf[mi][ks][2] = v0 ? q32[r0 * 16 + ks * 8 + q4 + 4] : 0u;
            qf[mi][ks][3] = v1 ? q32[r1 * 16 + ks * 8 + q4 + 4] : 0u;
        }
    }

    float Oa[2][4][4];
#pragma unroll
    for (int mi = 0; mi < 2; mi++)
#pragma unroll
        for (int ne = 0; ne < 4; ne++)
#pragma unroll
            for (int e = 0; e < 4; e++) Oa[mi][ne][e] = 0.f;
    float m_[2][2] = {{-1e30f, -1e30f}, {-1e30f, -1e30f}};
    float l_[2][2] = {{0.f, 0.f}, {0.f, 0.f}};
    const float scale = 0.17677669529663689f;

    for (int kt = 0; kt < NKT; kt++) {
        float sc[2][4][4];
#pragma unroll
        for (int mi = 0; mi < 2; mi++)
#pragma unroll
            for (int ni = 0; ni < 4; ni++)
#pragma unroll
                for (int e = 0; e < 4; e++) sc[mi][ni][e] = 0.f;

        uint32_t kf[2][4][2];
#pragma unroll
        for (int ks = 0; ks < 2; ks++)
#pragma unroll
            for (int ni = 0; ni < 4; ni++) {
                int r = kt * 32 + ni * 8 + g;
                kf[ks][ni][0] = Ks[r * KSTR + ks * 8 + q4];
                kf[ks][ni][1] = Ks[r * KSTR + ks * 8 + q4 + 4];
            }
#pragma unroll
        for (int mi = 0; mi < 2; mi++)
#pragma unroll
            for (int ni = 0; ni < 4; ni++)
#pragma unroll
                for (int ks = 0; ks < 2; ks++)
                    mma_bf16(sc[mi][ni], qf[mi][ks], kf[ks][ni]);

#pragma unroll
        for (int mi = 0; mi < 2; mi++) {
#pragma unroll
            for (int hf = 0; hf < 2; hf++) {
                float mx = -1e30f;
#pragma unroll
                for (int ni = 0; ni < 4; ni++) {
                    int col = kt * 32 + ni * 8 + q4 * 2;
                    float s0 = (col     < SEQ) ? sc[mi][ni][hf * 2]     * scale : -1e30f;
                    float s1 = (col + 1 < SEQ) ? sc[mi][ni][hf * 2 + 1] * scale : -1e30f;
                    sc[mi][ni][hf * 2]     = s0;
                    sc[mi][ni][hf * 2 + 1] = s1;
                    mx = fmaxf(mx, fmaxf(s0, s1));
                }
                mx = fmaxf(mx, __shfl_xor_sync(0xffffffffu, mx, 1));
                mx = fmaxf(mx, __shfl_xor_sync(0xffffffffu, mx, 2));
                float mnew = fmaxf(m_[mi][hf], mx);
                float f = __expf(m_[mi][hf] - mnew);
                m_[mi][hf] = mnew;
                float rs = 0.f;
#pragma unroll
                for (int ni = 0; ni < 4; ni++) {
                    float p0 = __expf(sc[mi][ni][hf * 2]     - mnew);
                    float p1 = __expf(sc[mi][ni][hf * 2 + 1] - mnew);
                    sc[mi][ni][hf * 2]     = p0;
                    sc[mi][ni][hf * 2 + 1] = p1;
                    rs += p0 + p1;
                }
                rs += __shfl_xor_sync(0xffffffffu, rs, 1);
                rs += __shfl_xor_sync(0xffffffffu, rs, 2);
                l_[mi][hf] = l_[mi][hf] * f + rs;
#pragma unroll
                for (int ne = 0; ne < 4; ne++) {
                    Oa[mi][ne][hf * 2]     *= f;
                    Oa[mi][ne][hf * 2 + 1] *= f;
                }
            }
        }

        uint32_t pa[2][2][4];
#pragma unroll
        for (int mi = 0; mi < 2; mi++)
#pragma unroll
            for (int ks = 0; ks < 2; ks++) {
                __nv_bfloat162 t0 = __floats2bfloat162_rn(sc[mi][2 * ks][0],     sc[mi][2 * ks][1]);
                __nv_bfloat162 t1 = __floats2bfloat162_rn(sc[mi][2 * ks][2],     sc[mi][2 * ks][3]);
                __nv_bfloat162 t2 = __floats2bfloat162_rn(sc[mi][2 * ks + 1][0], sc[mi][2 * ks + 1][1]);
                __nv_bfloat162 t3 = __floats2bfloat162_rn(sc[mi][2 * ks + 1][2], sc[mi][2 * ks + 1][3]);
                pa[mi][ks][0] = *reinterpret_cast<uint32_t*>(&t0);
                pa[mi][ks][1] = *reinterpret_cast<uint32_t*>(&t1);
                pa[mi][ks][2] = *reinterpret_cast<uint32_t*>(&t2);
                pa[mi][ks][3] = *reinterpret_cast<uint32_t*>(&t3);
            }

        uint32_t vf[2][4][2];
#pragma unroll
        for (int ks = 0; ks < 2; ks++)
#pragma unroll
            for (int ne = 0; ne < 4; ne++) {
                int r = ne * 8 + g;
                int cu = kt * 16 + ks * 8 + q4;
                vf[ks][ne][0] = VT[r * VSTR + cu];
                vf[ks][ne][1] = VT[r * VSTR + cu + 4];
            }
#pragma unroll
        for (int mi = 0; mi < 2; mi++)
#pragma unroll
            for (int ne = 0; ne < 4; ne++)
#pragma unroll
                for (int ks = 0; ks < 2; ks++)
                    mma_bf16(Oa[mi][ne], pa[mi][ks], vf[ks][ne]);
    }

#pragma unroll
    for (int mi = 0; mi < 2; mi++) {
#pragma unroll
        for (int hf = 0; hf < 2; hf++) {
            int row = qbase + mi * 16 + hf * 8 + g;
            if (row >= SEQ) continue;
            float inv = 1.f / l_[mi][hf];
            bf16* op = o + ((size_t)n * SEQ + row) * DMODEL + h * DH;
#pragma unroll
            for (int ne = 0; ne < 4; ne++) {
                __nv_bfloat162 p = __floats2bfloat162_rn(Oa[mi][ne][hf * 2] * inv,
                                                         Oa[mi][ne][hf * 2 + 1] * inv);
                *reinterpret_cast<uint32_t*>(op + ne * 8 + q4 * 2) = *reinterpret_cast<uint32_t*>(&p);
            }
        }
    }
}

// ---------------- classification head ---------------------------------------
__global__ void head_kernel(const float* __restrict__ X, const float* __restrict__ w_out,
                            const float* __restrict__ b_out, float* __restrict__ out)
{
    __shared__ float cls_s[DMODEL];
    __shared__ float logits[OUTC];
    __shared__ float red[8];
    const int n = blockIdx.x;
    const int t = threadIdx.x, wid = t >> 5, lane = t & 31;

    cls_s[t] = X[(size_t)n * SEQ * DMODEL + t];
    __syncthreads();

    for (int j = wid; j < OUTC; j += 8) {
        float acc = 0.f;
#pragma unroll
        for (int k = lane; k < DMODEL; k += 32) acc += cls_s[k] * w_out[(size_t)j * DMODEL + k];
#pragma unroll
        for (int off = 16; off; off >>= 1) acc += __shfl_xor_sync(0xffffffffu, acc, off);
        if (lane == 0) logits[j] = acc + b_out[j];
    }
    __syncthreads();

    float mx = -1e30f;
    for (int j = t; j < OUTC; j += 256) mx = fmaxf(mx, logits[j]);
#pragma unroll
    for (int off = 16; off; off >>= 1) mx = fmaxf(mx, __shfl_xor_sync(0xffffffffu, mx, off));
    if (lane == 0) red[wid] = mx;
    __syncthreads();
    float bm = -1e30f;
#pragma unroll
    for (int i = 0; i < 8; i++) bm = fmaxf(bm, red[i]);
    __syncthreads();

    float sum = 0.f;
    for (int j = t; j < OUTC; j += 256) {
        float e = __expf(logits[j] - bm);
        logits[j] = e;
        sum += e;
    }
#pragma unroll
    for (int off = 16; off; off >>= 1) sum += __shfl_xor_sync(0xffffffffu, sum, off);
    if (lane == 0) red[wid] = sum;
    __syncthreads();
    float bs = 0.f;
#pragma unroll
    for (int i = 0; i < 8; i++) bs += red[i];
    float inv = 1.f / bs;
    __syncthreads();
    for (int j = t; j < OUTC; j += 256) out[(size_t)n * OUTC + j] = logits[j] * inv;
}

// ---------------- launcher ----------------
extern "C" void kernel_launch(void* const* d_in, const int* in_sizes, int n_in,
                              void* d_out, int out_size)
{
    const float* images  = (const float*)d_in[0];
    const float* w_map   = (const float*)d_in[1];
    const float* b_map   = (const float*)d_in[2];
    const float* cls_tok = (const float*)d_in[3];
    const float* norm1_g = (const float*)d_in[4];
    const float* norm1_b = (const float*)d_in[5];
    const float* wq      = (const float*)d_in[6];
    const float* bq      = (const float*)d_in[7];
    const float* wk      = (const float*)d_in[8];
    const float* bk      = (const float*)d_in[9];
    const float* wv      = (const float*)d_in[10];
    const float* bv      = (const float*)d_in[11];
    const float* w_last  = (const float*)d_in[12];
    const float* b_last  = (const float*)d_in[13];
    const float* norm2_g = (const float*)d_in[14];
    const float* norm2_b = (const float*)d_in[15];
    const float* w_mlp1  = (const float*)d_in[16];
    const float* b_mlp1  = (const float*)d_in[17];
    const float* w_mlp2  = (const float*)d_in[18];
    const float* b_mlp2  = (const float*)d_in[19];
    const float* w_out   = (const float*)d_in[20];
    const float* b_out   = (const float*)d_in[21];
    float* out = (float*)d_out;

    bf16 *patches, *x1b, *qb, *kb, *vb, *ob, *h1b, *wmapb, *wlastb, *wmlp1b, *wmlp2b;
    float *X, *pe;
    cudaGetSymbolAddress((void**)&patches, g_patches_b);
    cudaGetSymbolAddress((void**)&X,   g_X);
    cudaGetSymbolAddress((void**)&x1b, g_x1b);
    cudaGetSymbolAddress((void**)&qb,  g_qb);
    cudaGetSymbolAddress((void**)&kb,  g_kb);
    cudaGetSymbolAddress((void**)&vb,  g_vb);
    cudaGetSymbolAddress((void**)&ob,  g_ob);
    cudaGetSymbolAddress((void**)&h1b, g_h1b);
    cudaGetSymbolAddress((void**)&pe,  g_pe);
    cudaGetSymbolAddress((void**)&wmapb,  g_wmapb);
    cudaGetSymbolAddress((void**)&wlastb, g_wlastb);
    cudaGetSymbolAddress((void**)&wmlp1b, g_wmlp1b);
    cudaGetSymbolAddress((void**)&wmlp2b, g_wmlp2b);

    cudaFuncSetAttribute(gemm_bf<0, false, false, true >, cudaFuncAttributeMaxDynamicSharedMemorySize, GEMM_SMEM);
    cudaFuncSetAttribute(gemm_bf<0, true,  false, false>, cudaFuncAttributeMaxDynamicSharedMemorySize, GEMM_SMEM);
    cudaFuncSetAttribute(gemm_bf<1, false, true,  false>, cudaFuncAttributeMaxDynamicSharedMemorySize, GEMM_SMEM);

    // 0) weight conversion to bf16
    {
        int n1 = DMODEL * IN_D;
        cvt_kernel<<<(n1 / 4 + 255) / 256, 256>>>(w_map, wmapb, n1);
        int n2 = NLAYER * DMODEL * DMODEL;
        cvt_kernel<<<(n2 / 4 + 255) / 256, 256>>>(w_last, wlastb, n2);
        int n3 = NLAYER * 4 * DMODEL * DMODEL;
        cvt_kernel<<<(n3 / 4 + 255) / 256, 256>>>(w_mlp1, wmlp1b, n3);
        cvt_kernel<<<(n3 / 4 + 255) / 256, 256>>>(w_mlp2, wmlp2b, n3);
    }

    // 1) patches + PE table
    {
        int tot = BATCH * NP * IN_D;
        patch_kernel<<<(tot + 255) / 256, 256>>>(images, patches);
        int pt = SEQ * DMODEL;
        pe_kernel<<<(pt + 255) / 256, 256>>>(pe);
    }

    // 2) patch-embed GEMM fused with assemble: X[n][p+1][:] = patches@w_map^T + b + pe
    gemm_bf<0, false, false, true><<<dim3(DMODEL / 128, (BATCH * NP) / 128), 256, GEMM_SMEM>>>(
        patches, wmapb, b_map, nullptr, pe, X, BATCH * NP, DMODEL, IN_D);

    // 2b) cls rows
    cls_kernel<<<(BATCH * DMODEL + 255) / 256, 256>>>(cls_tok, pe, X);

    const int MROWS = BATCH * SEQ;   // 25216 = 128*197

    for (int l = 0; l < NLAYER; l++) {
        ln_kernel<<<MROWS / 8, 256>>>(X, norm1_g + l * DMODEL, norm1_b + l * DMODEL, x1b);

        qkv_kernel<<<dim3(BATCH * NHEAD, (SEQ + 7) / 8), 256>>>(
            x1b,
            wq + (size_t)l * NHEAD * DH * DH, bq + (size_t)l * NHEAD * DH,
            wk + (size_t)l * NHEAD * DH * DH, bk + (size_t)l * NHEAD * DH,
            wv + (size_t)l * NHEAD * DH * DH, bv + (size_t)l * NHEAD * DH,
            qb, kb, vb);

        attn_tc<<<BATCH * NHEAD, 224>>>(qb, kb, vb, ob);

        // o-proj + residual: X = X + o @ w_last^T + b_last (25216,256,256)
        gemm_bf<0, true, false, false><<<dim3(DMODEL / 128, MROWS / 128), 256, GEMM_SMEM>>>(
            ob, wlastb + (size_t)l * DMODEL * DMODEL, b_last + l * DMODEL, X, nullptr, X,
            MROWS, DMODEL, DMODEL);

        ln_kernel<<<MROWS / 8, 256>>>(X, norm2_g + l * DMODEL, norm2_b + l * DMODEL, x1b);

        // MLP1 + GELU -> bf16 h1 (25216,1024,256)
        gemm_bf<1, false, true, false><<<dim3((4 * DMODEL) / 128, MROWS / 128), 256, GEMM_SMEM>>>(
            x1b, wmlp1b + (size_t)l * 4 * DMODEL * DMODEL, b_mlp1 + l * 4 * DMODEL,
            nullptr, nullptr, h1b, MROWS, 4 * DMODEL, DMODEL);

        // MLP2 + residual: X = X + h1 @ w_mlp2^T + b2 (25216,256,1024)
        gemm_bf<0, true, false, false><<<dim3(DMODEL / 128, MROWS / 128), 256, GEMM_SMEM>>>(
            h1b, wmlp2b + (size_t)l * 4 * DMODEL * DMODEL, b_mlp2 + l * DMODEL, X, nullptr, X,
            MROWS, DMODEL, 4 * DMODEL);
    }

    head_kernel<<<BATCH, 256>>>(X, w_out, b_out, out);
}